// round 10
// baseline (speedup 1.0000x reference)
#include <cuda_runtime.h>
#include <math.h>
#include <stdint.h>

#define BATCH  2
#define SEQ    8192
#define DMODEL 512
#define NH     8
#define HD     64
#define DHID   2048
#define BH     (BATCH*NH)     /* 16    */
#define MROWS  (BATCH*SEQ)    /* 16384 */

/* ---------------- scratch: __device__ globals only ---------------- */
__device__ float g_q[BH*SEQ*HD];
__device__ float g_k[BH*SEQ*HD];
__device__ float g_v[BH*SEQ*HD];
__device__ float g_attn[MROWS*DMODEL];
__device__ float g_h[MROWS*DMODEL];      /* stored tf32-rounded */
__device__ float g_ff1[MROWS*DHID];      /* stored tf32-rounded */
__device__ float g_ff2[MROWS*DMODEL];
__device__ float g_inv[BH*SEQ];
/* pre-rounded tf32 operand buffers */
__device__ float g_xt[MROWS*DMODEL];
__device__ float g_wq[DMODEL*DMODEL];
__device__ float g_wk[DMODEL*DMODEL];
__device__ float g_wv[DMODEL*DMODEL];
__device__ float g_w1[DMODEL*DHID];
__device__ float g_w2[DHID*DMODEL];

__device__ __forceinline__ uint32_t smem_u32(const void* p) {
    uint32_t a;
    asm("{ .reg .u64 t; cvta.to.shared.u64 t, %1; cvt.u32.u64 %0, t; }"
        : "=r"(a) : "l"(p));
    return a;
}
__device__ __forceinline__ uint32_t cvt_tf32(float x) {
    uint32_t r; asm("cvt.rna.tf32.f32 %0, %1;" : "=r"(r) : "f"(x)); return r;
}
__device__ __forceinline__ float round_tf32(float x) {
    return __uint_as_float(cvt_tf32(x));
}
__device__ __forceinline__ void mma_tf32(
    float& c0, float& c1, float& c2, float& c3,
    uint32_t a0, uint32_t a1, uint32_t a2, uint32_t a3,
    uint32_t b0, uint32_t b1)
{
    asm volatile(
        "mma.sync.aligned.m16n8k8.row.col.f32.tf32.tf32.f32 "
        "{%0,%1,%2,%3}, {%4,%5,%6,%7}, {%8,%9}, {%0,%1,%2,%3};"
        : "+f"(c0), "+f"(c1), "+f"(c2), "+f"(c3)
        : "r"(a0), "r"(a1), "r"(a2), "r"(a3), "r"(b0), "r"(b1));
}
__device__ __forceinline__ void cp16(uint32_t dst, const void* src) {
    asm volatile("cp.async.cg.shared.global [%0], [%1], 16;"
                 :: "r"(dst), "l"(src));
}
#define CP_COMMIT()   asm volatile("cp.async.commit_group;" ::: "memory")
#define CP_WAIT_ALL() asm volatile("cp.async.wait_group 0;" ::: "memory")

#define PA 20    /* A smem pitch: banks (20*gr+tg)%32 distinct over warp  */
#define PB 136   /* B smem pitch: banks (8*tg+gr)%32 distinct over warp   */
#define BK 16
#define STG_FLOATS (128*PA + BK*PB)            /* 4736 floats            */
/* static smem: 2 stages * 18944 B = 37888 B  (<48KB, no attr needed)    */

/* ================= tf32 pre-round copy kernel ================= */
__global__ void __launch_bounds__(256) cvt_copy(
    const float* __restrict__ src, float* __restrict__ dst, int n4)
{
    int i = blockIdx.x * 256 + threadIdx.x;
    if (i < n4) {
        float4 v = ((const float4*)src)[i];
        v.x = round_tf32(v.x); v.y = round_tf32(v.y);
        v.z = round_tf32(v.z); v.w = round_tf32(v.w);
        ((float4*)dst)[i] = v;
    }
}

/* =================================================================
 * tf32 warp-MMA GEMM, tile 128x128x16, 256 thr (2x4 warps, 64x32 warp
 * tile), 2-stage cp.async, ONE barrier per chunk, operands pre-rounded
 * to tf32 in gmem (no cvt in mainloop).
 * MODE 0: QKV (blockIdx.z selects q/k/v; A=g_xt, per-head epilogue)
 * MODE 1: FFN1 g_ff1 = tf32(relu(g_h @ W1 + b))
 * MODE 2: FFN2 g_ff2 = g_ff1 @ W2 + b
 * ================================================================= */
template<int MODE>
__global__ void __launch_bounds__(256) mma_gemm(
    const float* __restrict__ b0p,
    const float* __restrict__ b1p,
    const float* __restrict__ b2p)
{
    constexpr int N = (MODE == 1) ? DHID : DMODEL;
    constexpr int K = (MODE == 2) ? DHID : DMODEL;
    constexpr int NIT = K / BK;

    __shared__ uint32_t smp[2 * STG_FLOATS];
    const uint32_t sbase = smem_u32(smp);

    const int tid  = threadIdx.x;
    const int wid  = tid >> 5;
    const int lane = tid & 31;
    const int gr   = lane >> 2;
    const int tg   = lane & 3;
    const int wm   = wid & 1;
    const int wn   = wid >> 1;
    const int m0   = blockIdx.y * 128;
    const int n0   = blockIdx.x * 128;

    const float* Ag; const float* Bg; const float* bias;
    if (MODE == 0) {
        Ag = g_xt;
        if (blockIdx.z == 0)      { Bg = g_wq; bias = b0p; }
        else if (blockIdx.z == 1) { Bg = g_wk; bias = b1p; }
        else                      { Bg = g_wv; bias = b2p; }
    } else if (MODE == 1) { Ag = g_h;   Bg = g_w1; bias = b0p; }
    else                  { Ag = g_ff1; Bg = g_w2; bias = b0p; }

    float acc[4][4][4];
#pragma unroll
    for (int i = 0; i < 4; i++)
#pragma unroll
        for (int j = 0; j < 4; j++)
#pragma unroll
            for (int r = 0; r < 4; r++) acc[i][j][r] = 0.f;

    const int arow0 = tid >> 2,  ac4 = (tid & 3);          /* +64 rows  */
    const int brow0 = tid >> 5,  bc4 = (tid & 31);         /* +8 rows   */

#define ISSUE(cc, ss)                                                        \
    do {                                                                     \
        const int _k0 = (cc) * BK;                                           \
        const uint32_t _ab = sbase + (uint32_t)((ss) * STG_FLOATS) * 4u;     \
        const uint32_t _bb = _ab + (uint32_t)(128 * PA) * 4u;                \
        cp16(_ab + (uint32_t)(arow0 * PA + ac4 * 4) * 4u,                    \
             Ag + (size_t)(m0 + arow0) * K + _k0 + ac4 * 4);                 \
        cp16(_ab + (uint32_t)((arow0 + 64) * PA + ac4 * 4) * 4u,             \
             Ag + (size_t)(m0 + arow0 + 64) * K + _k0 + ac4 * 4);            \
        cp16(_bb + (uint32_t)(brow0 * PB + bc4 * 4) * 4u,                    \
             Bg + (size_t)(_k0 + brow0) * N + n0 + bc4 * 4);                 \
        cp16(_bb + (uint32_t)((brow0 + 8) * PB + bc4 * 4) * 4u,              \
             Bg + (size_t)(_k0 + brow0 + 8) * N + n0 + bc4 * 4);             \
    } while (0)

    /* prologue */
    ISSUE(0, 0);
    CP_COMMIT();

    for (int c = 0; c < NIT; c++) {
        CP_WAIT_ALL();               /* chunk c resident (own ops)       */
        __syncthreads();             /* visibility + stage-reuse fence   */
        if (c + 1 < NIT) {
            ISSUE(c + 1, (c + 1) & 1);
        }
        CP_COMMIT();

        const uint32_t* sA = smp + (c & 1) * STG_FLOATS;
        const uint32_t* sB = sA + 128 * PA;

#pragma unroll
        for (int kf = 0; kf < 2; kf++) {
            uint32_t a[4][4], b[4][2];
#pragma unroll
            for (int mf = 0; mf < 4; mf++) {
                const uint32_t* ap = &sA[(wm*64 + mf*16 + gr) * PA + kf*8 + tg];
                a[mf][0] = ap[0];
                a[mf][1] = ap[8 * PA];
                a[mf][2] = ap[4];
                a[mf][3] = ap[8 * PA + 4];
            }
#pragma unroll
            for (int nf = 0; nf < 4; nf++) {
                const uint32_t* bp = &sB[(kf*8 + tg) * PB + wn*32 + nf*8 + gr];
                b[nf][0] = bp[0];
                b[nf][1] = bp[4 * PB];
            }
#pragma unroll
            for (int mf = 0; mf < 4; mf++)
#pragma unroll
                for (int nf = 0; nf < 4; nf++)
                    mma_tf32(acc[mf][nf][0], acc[mf][nf][1],
                             acc[mf][nf][2], acc[mf][nf][3],
                             a[mf][0], a[mf][1], a[mf][2], a[mf][3],
                             b[nf][0], b[nf][1]);
        }
    }
#undef ISSUE

    /* ---------------- epilogue ---------------- */
#pragma unroll
    for (int mf = 0; mf < 4; mf++) {
#pragma unroll
        for (int nf = 0; nf < 4; nf++) {
            int mrow = m0 + wm*64 + mf*16 + gr;
            int ncol = n0 + wn*32 + nf*8 + 2*tg;
            float bx = bias[ncol], by = bias[ncol+1];
            float2 r0 = make_float2(acc[mf][nf][0] + bx, acc[mf][nf][1] + by);
            float2 r1 = make_float2(acc[mf][nf][2] + bx, acc[mf][nf][3] + by);
            if (MODE == 0) {
                const float scale = (blockIdx.z == 0) ? 0.125f : 1.f;
                float* outp = (blockIdx.z == 0) ? g_q
                            : ((blockIdx.z == 1) ? g_k : g_v);
                r0.x *= scale; r0.y *= scale; r1.x *= scale; r1.y *= scale;
                int h = ncol >> 6, d = ncol & 63;
                {
                    int bb = mrow >> 13, s = mrow & (SEQ-1);
                    *(float2*)&outp[(((size_t)bb*NH + h)*SEQ + s)*HD + d] = r0;
                }
                {
                    int m2 = mrow + 8;
                    int bb = m2 >> 13, s = m2 & (SEQ-1);
                    *(float2*)&outp[(((size_t)bb*NH + h)*SEQ + s)*HD + d] = r1;
                }
            } else {
                float* Cg = (MODE == 1) ? g_ff1 : g_ff2;
                if (MODE == 1) {
                    /* relu + pre-round to tf32 (feeds FFN2 A operand) */
                    r0.x = round_tf32(fmaxf(r0.x, 0.f));
                    r0.y = round_tf32(fmaxf(r0.y, 0.f));
                    r1.x = round_tf32(fmaxf(r1.x, 0.f));
                    r1.y = round_tf32(fmaxf(r1.y, 0.f));
                }
                *(float2*)&Cg[(size_t)mrow * N + ncol] = r0;
                *(float2*)&Cg[(size_t)(mrow+8) * N + ncol] = r1;
            }
        }
    }
}

/* =================================================================
 * Sliding-window attention (unchanged, passing version)
 * ================================================================= */
__global__ void __launch_bounds__(256) attn_kernel(float* __restrict__ out_score)
{
    __shared__ float qT[64*68];
    __shared__ float kT[64*34];
    __shared__ float vs[32*64];
    __shared__ float pt[64*33];
    __shared__ float invs[64];

    const int tid = threadIdx.x;
    const int bh  = blockIdx.y;
    const int q0  = blockIdx.x * 64;
    const float* qg = g_q + (size_t)bh * SEQ * HD;
    const float* kg = g_k + (size_t)bh * SEQ * HD;
    const float* vg = g_v + (size_t)bh * SEQ * HD;

    for (int i = tid; i < 64 * 16; i += 256) {
        int row = i >> 4;
        int c4  = (i & 15) * 4;
        float4 v = *(const float4*)(qg + (size_t)(q0 + row) * HD + c4);
        qT[(c4+0)*68 + row] = v.x;
        qT[(c4+1)*68 + row] = v.y;
        qT[(c4+2)*68 + row] = v.z;
        qT[(c4+3)*68 + row] = v.w;
    }

    const int xs = (tid & 15) * 4;
    const int yk = (tid >> 4) * 2;
    const int dx = (tid & 15) * 4;
    const int xr = (tid >> 4) * 4;

    float acc2[4][4];
#pragma unroll
    for (int i = 0; i < 4; i++)
#pragma unroll
        for (int j = 0; j < 4; j++) acc2[i][j] = 0.f;
    float psum[4] = {0.f, 0.f, 0.f, 0.f};

    for (int t = 0; t < 10; t++) {
        __syncthreads();
        const int gbase = q0 - 128 + t * 32;
        for (int i = tid; i < 32 * 16; i += 256) {
            int row = i >> 4;
            int c4  = (i & 15) * 4;
            int g = gbase + row;
            float4 kk = make_float4(0.f,0.f,0.f,0.f);
            float4 vv = make_float4(0.f,0.f,0.f,0.f);
            if (g >= 0 && g < SEQ) {
                kk = *(const float4*)(kg + (size_t)g * HD + c4);
                vv = *(const float4*)(vg + (size_t)g * HD + c4);
            }
            kT[(c4+0)*34 + row] = kk.x;
            kT[(c4+1)*34 + row] = kk.y;
            kT[(c4+2)*34 + row] = kk.z;
            kT[(c4+3)*34 + row] = kk.w;
            *(float4*)&vs[row*64 + c4] = vv;
        }
        __syncthreads();

        float acc[2][4];
#pragma unroll
        for (int i = 0; i < 2; i++)
#pragma unroll
            for (int j = 0; j < 4; j++) acc[i][j] = 0.f;
#pragma unroll 4
        for (int d = 0; d < 64; d++) {
            float2 kk = *(const float2*)&kT[d*34 + yk];
            float4 qv = *(const float4*)&qT[d*68 + xs];
            acc[0][0] += kk.x * qv.x;  acc[0][1] += kk.x * qv.y;
            acc[0][2] += kk.x * qv.z;  acc[0][3] += kk.x * qv.w;
            acc[1][0] += kk.y * qv.x;  acc[1][1] += kk.y * qv.y;
            acc[1][2] += kk.y * qv.z;  acc[1][3] += kk.y * qv.w;
        }
#pragma unroll
        for (int i = 0; i < 2; i++) {
            int ylocal = t*32 + yk + i;
            int g = q0 - 128 + ylocal;
#pragma unroll
            for (int j = 0; j < 4; j++) {
                int xq = xs + j;
                int jb = ylocal - xq;
                float e = 0.f;
                if (jb >= 0 && jb <= 256 && g >= 0 && g < SEQ)
                    e = expf(acc[i][j]);
                pt[xq*33 + yk + i] = e;
                psum[j] += e;
            }
        }
        __syncthreads();

        {
            float* osc = out_score + ((size_t)bh * SEQ + q0) * 257;
            for (int i = tid; i < 64 * 32; i += 256) {
                int q = i >> 5;
                int k = i & 31;
                int jb = t*32 + k - q;
                if (jb >= 0 && jb <= 256)
                    osc[(size_t)q * 257 + jb] = pt[q*33 + k];
            }
        }
#pragma unroll 4
        for (int yy = 0; yy < 32; yy++) {
            float4 v4 = *(const float4*)&vs[yy*64 + dx];
            float a0 = pt[(xr+0)*33 + yy];
            float a1 = pt[(xr+1)*33 + yy];
            float a2 = pt[(xr+2)*33 + yy];
            float a3 = pt[(xr+3)*33 + yy];
            acc2[0][0] += a0*v4.x; acc2[0][1] += a0*v4.y; acc2[0][2] += a0*v4.z; acc2[0][3] += a0*v4.w;
            acc2[1][0] += a1*v4.x; acc2[1][1] += a1*v4.y; acc2[1][2] += a1*v4.z; acc2[1][3] += a1*v4.w;
            acc2[2][0] += a2*v4.x; acc2[2][1] += a2*v4.y; acc2[2][2] += a2*v4.z; acc2[2][3] += a2*v4.w;
            acc2[3][0] += a3*v4.x; acc2[3][1] += a3*v4.y; acc2[3][2] += a3*v4.z; acc2[3][3] += a3*v4.w;
        }
    }

    __syncthreads();
#pragma unroll
    for (int j = 0; j < 4; j++)
        pt[(tid >> 4)*64 + xs + j] = psum[j];
    __syncthreads();
    if (tid < 64) {
        float s = 0.f;
        for (int r = 0; r < 16; r++) s += pt[r*64 + tid];
        float iv = 1.f / s;
        invs[tid] = iv;
        g_inv[(size_t)bh * SEQ + q0 + tid] = iv;
    }
    __syncthreads();

    const int bb = bh >> 3;
    const int hh = bh & 7;
#pragma unroll
    for (int i = 0; i < 4; i++) {
        float iv = invs[xr + i];
        float4 r = make_float4(acc2[i][0]*iv, acc2[i][1]*iv,
                               acc2[i][2]*iv, acc2[i][3]*iv);
        *(float4*)&g_attn[((size_t)bb * SEQ + q0 + xr + i) * DMODEL + hh*HD + dx] = r;
    }
}

__global__ void __launch_bounds__(128) band_norm(float* __restrict__ out_score)
{
    const int row = blockIdx.x;
    const float iv = g_inv[row];
    float* p = out_score + (size_t)row * 257;
    for (int t = threadIdx.x; t < 257; t += 128)
        p[t] *= iv;
}

/* =================================================================
 * LayerNorm(a + b): MODE 0: g_h = tf32(LN(g_attn + x))
 *                   MODE 1: out = LN(g_ff2 + g_h)
 * ================================================================= */
template<int MODE>
__global__ void __launch_bounds__(128) ln_res(
    const float* __restrict__ xb,
    const float* __restrict__ gam, const float* __restrict__ bet,
    float* __restrict__ outp)
{
    const float* a = (MODE == 0) ? g_attn : g_ff2;
    const float* b = (MODE == 0) ? xb     : g_h;
    float* out     = (MODE == 0) ? g_h    : outp;

    __shared__ float sred[2][4];
    const int row = blockIdx.x;
    const int tid = threadIdx.x;
    const float4 va = ((const float4*)(a + (size_t)row * DMODEL))[tid];
    const float4 vb = ((const float4*)(b + (size_t)row * DMODEL))[tid];
    float4 v = make_float4(va.x+vb.x, va.y+vb.y, va.z+vb.z, va.w+vb.w);
    float s  = v.x + v.y + v.z + v.w;
    float sq = v.x*v.x + v.y*v.y + v.z*v.z + v.w*v.w;
#pragma unroll
    for (int o = 16; o > 0; o >>= 1) {
        s  += __shfl_down_sync(0xFFFFFFFFu, s,  o);
        sq += __shfl_down_sync(0xFFFFFFFFu, sq, o);
    }
    if ((tid & 31) == 0) { sred[0][tid >> 5] = s; sred[1][tid >> 5] = sq; }
    __syncthreads();
    s  = sred[0][0] + sred[0][1] + sred[0][2] + sred[0][3];
    sq = sred[1][0] + sred[1][1] + sred[1][2] + sred[1][3];
    float mean = s * (1.f / DMODEL);
    float var  = sq * (1.f / DMODEL) - mean * mean;
    float rs   = rsqrtf(var + 1e-5f);
    float4 g4 = ((const float4*)gam)[tid];
    float4 b4 = ((const float4*)bet)[tid];
    float4 r;
    r.x = (v.x - mean) * rs * g4.x + b4.x;
    r.y = (v.y - mean) * rs * g4.y + b4.y;
    r.z = (v.z - mean) * rs * g4.z + b4.z;
    r.w = (v.w - mean) * rs * g4.w + b4.w;
    if (MODE == 0) {
        /* g_h feeds FFN1 A operand: pre-round to tf32 */
        r.x = round_tf32(r.x); r.y = round_tf32(r.y);
        r.z = round_tf32(r.z); r.w = round_tf32(r.w);
    }
    ((float4*)(out + (size_t)row * DMODEL))[tid] = r;
}

/* ================================================================= */
extern "C" void kernel_launch(void* const* d_in, const int* in_sizes, int n_in,
                              void* d_out, int out_size)
{
    const float* x    = (const float*)d_in[0];
    const float* Wq   = (const float*)d_in[1];
    const float* bq   = (const float*)d_in[2];
    const float* Wk   = (const float*)d_in[3];
    const float* bk   = (const float*)d_in[4];
    const float* Wv   = (const float*)d_in[5];
    const float* bv   = (const float*)d_in[6];
    const float* ln1g = (const float*)d_in[7];
    const float* ln1b = (const float*)d_in[8];
    const float* Wf1  = (const float*)d_in[9];
    const float* bf1  = (const float*)d_in[10];
    const float* Wf2  = (const float*)d_in[11];
    const float* bf2  = (const float*)d_in[12];
    const float* ln2g = (const float*)d_in[13];
    const float* ln2b = (const float*)d_in[14];
    (void)in_sizes; (void)n_in; (void)out_size;

    float* out       = (float*)d_out;                    /* [16384,512]   */
    float* out_score = out + (size_t)MROWS * DMODEL;     /* [16,8192,257] */

    float *pxt, *pwq, *pwk, *pwv, *pw1, *pw2;
    cudaGetSymbolAddress((void**)&pxt, g_xt);
    cudaGetSymbolAddress((void**)&pwq, g_wq);
    cudaGetSymbolAddress((void**)&pwk, g_wk);
    cudaGetSymbolAddress((void**)&pwv, g_wv);
    cudaGetSymbolAddress((void**)&pw1, g_w1);
    cudaGetSymbolAddress((void**)&pw2, g_w2);

    /* 0. pre-round operands to tf32 */
    cvt_copy<<<(MROWS*DMODEL/4 + 255)/256, 256>>>(x,   pxt, MROWS*DMODEL/4);
    cvt_copy<<<(DMODEL*DMODEL/4 + 255)/256, 256>>>(Wq, pwq, DMODEL*DMODEL/4);
    cvt_copy<<<(DMODEL*DMODEL/4 + 255)/256, 256>>>(Wk, pwk, DMODEL*DMODEL/4);
    cvt_copy<<<(DMODEL*DMODEL/4 + 255)/256, 256>>>(Wv, pwv, DMODEL*DMODEL/4);
    cvt_copy<<<(DMODEL*DHID/4 + 255)/256, 256>>>(Wf1, pw1, DMODEL*DHID/4);
    cvt_copy<<<(DHID*DMODEL/4 + 255)/256, 256>>>(Wf2, pw2, DHID*DMODEL/4);

    /* 1. QKV projections */
    mma_gemm<0><<<dim3(DMODEL/128, MROWS/128, 3), 256>>>(bq, bk, bv);
    /* 2. attention */
    attn_kernel<<<dim3(SEQ/64, BH), 256>>>(out_score);
    /* 3. normalize band */
    band_norm<<<BH*SEQ, 128>>>(out_score);
    /* 4. h = tf32(LN(attn + x)) */
    ln_res<0><<<MROWS, 128>>>(x, ln1g, ln1b, nullptr);
    /* 5. ff1 = tf32(relu(h @ Wf1 + bf1)) */
    mma_gemm<1><<<dim3(DHID/128, MROWS/128), 256>>>(bf1, nullptr, nullptr);
    /* 6. ff2 = ff1 @ Wf2 + bf2 */
    mma_gemm<2><<<dim3(DMODEL/128, MROWS/128), 256>>>(bf2, nullptr, nullptr);
    /* 7. out = LN(ff2 + h) */
    ln_res<1><<<MROWS, 128>>>(x, ln2g, ln2b, out);
}

// round 12
// speedup vs baseline: 1.2244x; 1.2244x over previous
#include <cuda_runtime.h>
#include <math.h>
#include <stdint.h>

#define BATCH  2
#define SEQ    8192
#define DMODEL 512
#define NH     8
#define HD     64
#define DHID   2048
#define BH     (BATCH*NH)     /* 16    */
#define MROWS  (BATCH*SEQ)    /* 16384 */

/* ---------------- scratch: __device__ globals only ---------------- */
__device__ float g_q[BH*SEQ*HD];
__device__ float g_k[BH*SEQ*HD];
__device__ float g_v[BH*SEQ*HD];
__device__ float g_attn[MROWS*DMODEL];
__device__ float g_h[MROWS*DMODEL];      /* stored tf32-rounded */
__device__ float g_ff1[MROWS*DHID];      /* stored tf32-rounded */
__device__ float g_ff2[MROWS*DMODEL];
__device__ float g_inv[BH*SEQ];
/* pre-rounded tf32 operand buffers */
__device__ float g_xt[MROWS*DMODEL];
__device__ float g_wq[DMODEL*DMODEL];
__device__ float g_wk[DMODEL*DMODEL];
__device__ float g_wv[DMODEL*DMODEL];
__device__ float g_w1[DMODEL*DHID];
__device__ float g_w2[DHID*DMODEL];

__device__ __forceinline__ uint32_t smem_u32(const void* p) {
    uint32_t a;
    asm("{ .reg .u64 t; cvta.to.shared.u64 t, %1; cvt.u32.u64 %0, t; }"
        : "=r"(a) : "l"(p));
    return a;
}
__device__ __forceinline__ uint32_t cvt_tf32(float x) {
    uint32_t r; asm("cvt.rna.tf32.f32 %0, %1;" : "=r"(r) : "f"(x)); return r;
}
__device__ __forceinline__ float round_tf32(float x) {
    return __uint_as_float(cvt_tf32(x));
}
__device__ __forceinline__ void mma_tf32(
    float& c0, float& c1, float& c2, float& c3,
    uint32_t a0, uint32_t a1, uint32_t a2, uint32_t a3,
    uint32_t b0, uint32_t b1)
{
    asm volatile(
        "mma.sync.aligned.m16n8k8.row.col.f32.tf32.tf32.f32 "
        "{%0,%1,%2,%3}, {%4,%5,%6,%7}, {%8,%9}, {%0,%1,%2,%3};"
        : "+f"(c0), "+f"(c1), "+f"(c2), "+f"(c3)
        : "r"(a0), "r"(a1), "r"(a2), "r"(a3), "r"(b0), "r"(b1));
}
__device__ __forceinline__ void cp16(uint32_t dst, const void* src) {
    asm volatile("cp.async.cg.shared.global [%0], [%1], 16;"
                 :: "r"(dst), "l"(src));
}
#define CP_COMMIT()   asm volatile("cp.async.commit_group;" ::: "memory")
#define CP_WAIT_ALL() asm volatile("cp.async.wait_group 0;" ::: "memory")

#define PA 20
#define PB 136
#define BK 16
#define STG_FLOATS (128*PA + BK*PB)            /* 4736 floats            */

/* ================= tf32 pre-round copy kernel ================= */
__global__ void __launch_bounds__(256) cvt_copy(
    const float* __restrict__ src, float* __restrict__ dst, int n4)
{
    int i = blockIdx.x * 256 + threadIdx.x;
    if (i < n4) {
        float4 v = ((const float4*)src)[i];
        v.x = round_tf32(v.x); v.y = round_tf32(v.y);
        v.z = round_tf32(v.z); v.w = round_tf32(v.w);
        ((float4*)dst)[i] = v;
    }
}

/* =================================================================
 * tf32 warp-MMA GEMM (unchanged from passing R10 version)
 * ================================================================= */
template<int MODE>
__global__ void __launch_bounds__(256) mma_gemm(
    const float* __restrict__ b0p,
    const float* __restrict__ b1p,
    const float* __restrict__ b2p)
{
    constexpr int N = (MODE == 1) ? DHID : DMODEL;
    constexpr int K = (MODE == 2) ? DHID : DMODEL;
    constexpr int NIT = K / BK;

    __shared__ uint32_t smp[2 * STG_FLOATS];
    const uint32_t sbase = smem_u32(smp);

    const int tid  = threadIdx.x;
    const int wid  = tid >> 5;
    const int lane = tid & 31;
    const int gr   = lane >> 2;
    const int tg   = lane & 3;
    const int wm   = wid & 1;
    const int wn   = wid >> 1;
    const int m0   = blockIdx.y * 128;
    const int n0   = blockIdx.x * 128;

    const float* Ag; const float* Bg; const float* bias;
    if (MODE == 0) {
        Ag = g_xt;
        if (blockIdx.z == 0)      { Bg = g_wq; bias = b0p; }
        else if (blockIdx.z == 1) { Bg = g_wk; bias = b1p; }
        else                      { Bg = g_wv; bias = b2p; }
    } else if (MODE == 1) { Ag = g_h;   Bg = g_w1; bias = b0p; }
    else                  { Ag = g_ff1; Bg = g_w2; bias = b0p; }

    float acc[4][4][4];
#pragma unroll
    for (int i = 0; i < 4; i++)
#pragma unroll
        for (int j = 0; j < 4; j++)
#pragma unroll
            for (int r = 0; r < 4; r++) acc[i][j][r] = 0.f;

    const int arow0 = tid >> 2,  ac4 = (tid & 3);
    const int brow0 = tid >> 5,  bc4 = (tid & 31);

#define ISSUE(cc, ss)                                                        \
    do {                                                                     \
        const int _k0 = (cc) * BK;                                           \
        const uint32_t _ab = sbase + (uint32_t)((ss) * STG_FLOATS) * 4u;     \
        const uint32_t _bb = _ab + (uint32_t)(128 * PA) * 4u;                \
        cp16(_ab + (uint32_t)(arow0 * PA + ac4 * 4) * 4u,                    \
             Ag + (size_t)(m0 + arow0) * K + _k0 + ac4 * 4);                 \
        cp16(_ab + (uint32_t)((arow0 + 64) * PA + ac4 * 4) * 4u,             \
             Ag + (size_t)(m0 + arow0 + 64) * K + _k0 + ac4 * 4);            \
        cp16(_bb + (uint32_t)(brow0 * PB + bc4 * 4) * 4u,                    \
             Bg + (size_t)(_k0 + brow0) * N + n0 + bc4 * 4);                 \
        cp16(_bb + (uint32_t)((brow0 + 8) * PB + bc4 * 4) * 4u,              \
             Bg + (size_t)(_k0 + brow0 + 8) * N + n0 + bc4 * 4);             \
    } while (0)

    ISSUE(0, 0);
    CP_COMMIT();

    for (int c = 0; c < NIT; c++) {
        CP_WAIT_ALL();
        __syncthreads();
        if (c + 1 < NIT) {
            ISSUE(c + 1, (c + 1) & 1);
        }
        CP_COMMIT();

        const uint32_t* sA = smp + (c & 1) * STG_FLOATS;
        const uint32_t* sB = sA + 128 * PA;

#pragma unroll
        for (int kf = 0; kf < 2; kf++) {
            uint32_t a[4][4], b[4][2];
#pragma unroll
            for (int mf = 0; mf < 4; mf++) {
                const uint32_t* ap = &sA[(wm*64 + mf*16 + gr) * PA + kf*8 + tg];
                a[mf][0] = ap[0];
                a[mf][1] = ap[8 * PA];
                a[mf][2] = ap[4];
                a[mf][3] = ap[8 * PA + 4];
            }
#pragma unroll
            for (int nf = 0; nf < 4; nf++) {
                const uint32_t* bp = &sB[(kf*8 + tg) * PB + wn*32 + nf*8 + gr];
                b[nf][0] = bp[0];
                b[nf][1] = bp[4 * PB];
            }
#pragma unroll
            for (int mf = 0; mf < 4; mf++)
#pragma unroll
                for (int nf = 0; nf < 4; nf++)
                    mma_tf32(acc[mf][nf][0], acc[mf][nf][1],
                             acc[mf][nf][2], acc[mf][nf][3],
                             a[mf][0], a[mf][1], a[mf][2], a[mf][3],
                             b[nf][0], b[nf][1]);
        }
    }
#undef ISSUE

#pragma unroll
    for (int mf = 0; mf < 4; mf++) {
#pragma unroll
        for (int nf = 0; nf < 4; nf++) {
            int mrow = m0 + wm*64 + mf*16 + gr;
            int ncol = n0 + wn*32 + nf*8 + 2*tg;
            float bx = bias[ncol], by = bias[ncol+1];
            float2 r0 = make_float2(acc[mf][nf][0] + bx, acc[mf][nf][1] + by);
            float2 r1 = make_float2(acc[mf][nf][2] + bx, acc[mf][nf][3] + by);
            if (MODE == 0) {
                const float scale = (blockIdx.z == 0) ? 0.125f : 1.f;
                float* outp = (blockIdx.z == 0) ? g_q
                            : ((blockIdx.z == 1) ? g_k : g_v);
                r0.x *= scale; r0.y *= scale; r1.x *= scale; r1.y *= scale;
                int h = ncol >> 6, d = ncol & 63;
                {
                    int bb = mrow >> 13, s = mrow & (SEQ-1);
                    *(float2*)&outp[(((size_t)bb*NH + h)*SEQ + s)*HD + d] = r0;
                }
                {
                    int m2 = mrow + 8;
                    int bb = m2 >> 13, s = m2 & (SEQ-1);
                    *(float2*)&outp[(((size_t)bb*NH + h)*SEQ + s)*HD + d] = r1;
                }
            } else {
                float* Cg = (MODE == 1) ? g_ff1 : g_ff2;
                if (MODE == 1) {
                    r0.x = round_tf32(fmaxf(r0.x, 0.f));
                    r0.y = round_tf32(fmaxf(r0.y, 0.f));
                    r1.x = round_tf32(fmaxf(r1.x, 0.f));
                    r1.y = round_tf32(fmaxf(r1.y, 0.f));
                }
                *(float2*)&Cg[(size_t)mrow * N + ncol] = r0;
                *(float2*)&Cg[(size_t)(mrow+8) * N + ncol] = r1;
            }
        }
    }
}

/* =================================================================
 * Tensor-core sliding-window attention.
 * Block = 64 queries of one (b,h); 10 key-tiles of 32.
 * 8 warps as 2(m)x4(n). QK^T: warp 32x8, K=64. PV: warp 32x16, K=32.
 * smem ~45.8KB static. Pitches: qs/ks 68 (banks 4*gr+tg), vs 72
 * (banks 8*tg+gr), pt 36 (banks 4*gr+tg) — all conflict-free.
 * ================================================================= */
__global__ void __launch_bounds__(256) attn_kernel(float* __restrict__ out_score)
{
    __shared__ uint32_t qs[64*68];
    __shared__ uint32_t ks[32*68];
    __shared__ uint32_t vs[32*72];
    __shared__ uint32_t pt[64*36];
    __shared__ float red[4][64];
    __shared__ float invs[64];

    const int tid = threadIdx.x;
    const int bh  = blockIdx.y;
    const int q0  = blockIdx.x * 64;
    const float* qg = g_q + (size_t)bh * SEQ * HD;
    const float* kg = g_k + (size_t)bh * SEQ * HD;
    const float* vg = g_v + (size_t)bh * SEQ * HD;

    /* load q tile (natural [q][d], tf32 bits) */
    for (int i = tid; i < 64 * 16; i += 256) {
        int row = i >> 4;
        int c4  = (i & 15) * 4;
        float4 v = *(const float4*)(qg + (size_t)(q0 + row) * HD + c4);
        uint4 t;
        t.x = cvt_tf32(v.x); t.y = cvt_tf32(v.y);
        t.z = cvt_tf32(v.z); t.w = cvt_tf32(v.w);
        *(uint4*)&qs[row*68 + c4] = t;
    }

    const int lane = tid & 31;
    const int wid  = tid >> 5;
    const int gr   = lane >> 2;
    const int tg   = lane & 3;
    const int wm   = wid & 1;        /* 0..1 -> 32 q rows */
    const int wn   = wid >> 1;       /* 0..3              */

    float accO[2][2][4];
#pragma unroll
    for (int i = 0; i < 2; i++)
#pragma unroll
        for (int j = 0; j < 2; j++)
#pragma unroll
            for (int r = 0; r < 4; r++) accO[i][j][r] = 0.f;
    /* psum index: mf*2+h -> q row wm*32 + mf*16 + h*8 + gr */
    float psum[4] = {0.f, 0.f, 0.f, 0.f};

    for (int t = 0; t < 10; t++) {
        __syncthreads();
        const int gbase = q0 - 128 + t * 32;
        /* load k, v tiles natural [key][d] tf32 */
        for (int i = tid; i < 32 * 16; i += 256) {
            int row = i >> 4;
            int c4  = (i & 15) * 4;
            int g = gbase + row;
            float4 kk = make_float4(0.f,0.f,0.f,0.f);
            float4 vv = make_float4(0.f,0.f,0.f,0.f);
            if (g >= 0 && g < SEQ) {
                kk = *(const float4*)(kg + (size_t)g * HD + c4);
                vv = *(const float4*)(vg + (size_t)g * HD + c4);
            }
            uint4 tk, tv;
            tk.x = cvt_tf32(kk.x); tk.y = cvt_tf32(kk.y);
            tk.z = cvt_tf32(kk.z); tk.w = cvt_tf32(kk.w);
            tv.x = cvt_tf32(vv.x); tv.y = cvt_tf32(vv.y);
            tv.z = cvt_tf32(vv.z); tv.w = cvt_tf32(vv.w);
            *(uint4*)&ks[row*68 + c4] = tk;
            *(uint4*)&vs[row*72 + c4] = tv;
        }
        __syncthreads();

        /* ---- QK^T: scores 64x32, warp tile 32x8, K=64 ---- */
        float sc[2][4];
#pragma unroll
        for (int i = 0; i < 2; i++)
#pragma unroll
            for (int r = 0; r < 4; r++) sc[i][r] = 0.f;
#pragma unroll
        for (int kf = 0; kf < 8; kf++) {
            uint32_t a[2][4], b[2];
#pragma unroll
            for (int mf = 0; mf < 2; mf++) {
                const uint32_t* ap = &qs[(wm*32 + mf*16 + gr)*68 + kf*8 + tg];
                a[mf][0] = ap[0];
                a[mf][1] = ap[8*68];
                a[mf][2] = ap[4];
                a[mf][3] = ap[8*68 + 4];
            }
            /* B(k=dim, n=key) = ks[key][dim] */
            const uint32_t* bp = &ks[(wn*8 + gr)*68 + kf*8 + tg];
            b[0] = bp[0];
            b[1] = bp[4];
#pragma unroll
            for (int mf = 0; mf < 2; mf++)
                mma_tf32(sc[mf][0], sc[mf][1], sc[mf][2], sc[mf][3],
                         a[mf][0], a[mf][1], a[mf][2], a[mf][3],
                         b[0], b[1]);
        }

        /* ---- exp + mask -> pt (tf32 bits), psum ---- */
#pragma unroll
        for (int mf = 0; mf < 2; mf++) {
            const int rb = wm*32 + mf*16 + gr;
            const int n0 = wn*8 + 2*tg;
#pragma unroll
            for (int h = 0; h < 2; h++) {
                const int r = rb + h*8;
#pragma unroll
                for (int cc = 0; cc < 2; cc++) {
                    const int kloc = n0 + cc;
                    const int jb = t*32 + kloc - r;
                    const int g  = gbase + kloc;
                    float e = 0.f;
                    if (jb >= 0 && jb <= 256 && g >= 0 && g < SEQ)
                        e = expf(sc[mf][h*2 + cc]);
                    pt[r*36 + kloc] = cvt_tf32(e);
                    psum[mf*2 + h] += e;
                }
            }
        }
        __syncthreads();

        /* ---- band write (unnormalized) ---- */
        {
            float* osc = out_score + ((size_t)bh * SEQ + q0) * 257;
#pragma unroll
            for (int i = tid; i < 64 * 32; i += 256) {
                int q = i >> 5;
                int k = i & 31;
                int jb = t*32 + k - q;
                if (jb >= 0 && jb <= 256)
                    osc[(size_t)q * 257 + jb] = __uint_as_float(pt[q*36 + k]);
            }
        }

        /* ---- PV: O += P(64x32) @ V(32x64), warp tile 32x16, K=32 ---- */
#pragma unroll
        for (int kf = 0; kf < 4; kf++) {
            uint32_t a[2][4], b[2][2];
#pragma unroll
            for (int mf = 0; mf < 2; mf++) {
                const uint32_t* ap = &pt[(wm*32 + mf*16 + gr)*36 + kf*8 + tg];
                a[mf][0] = ap[0];
                a[mf][1] = ap[8*36];
                a[mf][2] = ap[4];
                a[mf][3] = ap[8*36 + 4];
            }
            /* B(k=key, n=dim) = vs[key][dim] */
#pragma unroll
            for (int nf = 0; nf < 2; nf++) {
                const uint32_t* bp = &vs[(kf*8 + tg)*72 + wn*16 + nf*8 + gr];
                b[nf][0] = bp[0];
                b[nf][1] = bp[4*72];
            }
#pragma unroll
            for (int mf = 0; mf < 2; mf++)
#pragma unroll
                for (int nf = 0; nf < 2; nf++)
                    mma_tf32(accO[mf][nf][0], accO[mf][nf][1],
                             accO[mf][nf][2], accO[mf][nf][3],
                             a[mf][0], a[mf][1], a[mf][2], a[mf][3],
                             b[nf][0], b[nf][1]);
        }
    }

    /* ---- psum reduce: over tg lanes, then over wn warps ---- */
#pragma unroll
    for (int j = 0; j < 4; j++) {
        psum[j] += __shfl_xor_sync(0xFFFFFFFFu, psum[j], 1);
        psum[j] += __shfl_xor_sync(0xFFFFFFFFu, psum[j], 2);
    }
    if (tg == 0) {
#pragma unroll
        for (int j = 0; j < 4; j++) {
            int q = wm*32 + (j >> 1)*16 + (j & 1)*8 + gr;
            red[wn][q] = psum[j];
        }
    }
    __syncthreads();
    if (tid < 64) {
        float s = red[0][tid] + red[1][tid] + red[2][tid] + red[3][tid];
        float iv = 1.f / s;
        invs[tid] = iv;
        g_inv[(size_t)bh * SEQ + q0 + tid] = iv;
    }
    __syncthreads();

    /* ---- write attn out (heads re-merged) ---- */
    const int bb = bh >> 3;
    const int hh = bh & 7;
#pragma unroll
    for (int mf = 0; mf < 2; mf++) {
#pragma unroll
        for (int nf = 0; nf < 2; nf++) {
            int r  = wm*32 + mf*16 + gr;
            int d0 = wn*16 + nf*8 + 2*tg;
            float iv0 = invs[r];
            float iv1 = invs[r + 8];
            float2 o0 = make_float2(accO[mf][nf][0]*iv0, accO[mf][nf][1]*iv0);
            float2 o1 = make_float2(accO[mf][nf][2]*iv1, accO[mf][nf][3]*iv1);
            *(float2*)&g_attn[((size_t)bb*SEQ + q0 + r)     * DMODEL + hh*HD + d0] = o0;
            *(float2*)&g_attn[((size_t)bb*SEQ + q0 + r + 8) * DMODEL + hh*HD + d0] = o1;
        }
    }
}

__global__ void __launch_bounds__(128) band_norm(float* __restrict__ out_score)
{
    const int row = blockIdx.x;
    const float iv = g_inv[row];
    float* p = out_score + (size_t)row * 257;
    for (int t = threadIdx.x; t < 257; t += 128)
        p[t] *= iv;
}

/* =================================================================
 * LayerNorm(a + b): MODE 0: g_h = tf32(LN(g_attn + x))
 *                   MODE 1: out = LN(g_ff2 + g_h)
 * ================================================================= */
template<int MODE>
__global__ void __launch_bounds__(128) ln_res(
    const float* __restrict__ xb,
    const float* __restrict__ gam, const float* __restrict__ bet,
    float* __restrict__ outp)
{
    const float* a = (MODE == 0) ? g_attn : g_ff2;
    const float* b = (MODE == 0) ? xb     : g_h;
    float* out     = (MODE == 0) ? g_h    : outp;

    __shared__ float sred[2][4];
    const int row = blockIdx.x;
    const int tid = threadIdx.x;
    const float4 va = ((const float4*)(a + (size_t)row * DMODEL))[tid];
    const float4 vb = ((const float4*)(b + (size_t)row * DMODEL))[tid];
    float4 v = make_float4(va.x+vb.x, va.y+vb.y, va.z+vb.z, va.w+vb.w);
    float s  = v.x + v.y + v.z + v.w;
    float sq = v.x*v.x + v.y*v.y + v.z*v.z + v.w*v.w;
#pragma unroll
    for (int o = 16; o > 0; o >>= 1) {
        s  += __shfl_down_sync(0xFFFFFFFFu, s,  o);
        sq += __shfl_down_sync(0xFFFFFFFFu, sq, o);
    }
    if ((tid & 31) == 0) { sred[0][tid >> 5] = s; sred[1][tid >> 5] = sq; }
    __syncthreads();
    s  = sred[0][0] + sred[0][1] + sred[0][2] + sred[0][3];
    sq = sred[1][0] + sred[1][1] + sred[1][2] + sred[1][3];
    float mean = s * (1.f / DMODEL);
    float var  = sq * (1.f / DMODEL) - mean * mean;
    float rs   = rsqrtf(var + 1e-5f);
    float4 g4 = ((const float4*)gam)[tid];
    float4 b4 = ((const float4*)bet)[tid];
    float4 r;
    r.x = (v.x - mean) * rs * g4.x + b4.x;
    r.y = (v.y - mean) * rs * g4.y + b4.y;
    r.z = (v.z - mean) * rs * g4.z + b4.z;
    r.w = (v.w - mean) * rs * g4.w + b4.w;
    if (MODE == 0) {
        r.x = round_tf32(r.x); r.y = round_tf32(r.y);
        r.z = round_tf32(r.z); r.w = round_tf32(r.w);
    }
    ((float4*)(out + (size_t)row * DMODEL))[tid] = r;
}

/* ================================================================= */
extern "C" void kernel_launch(void* const* d_in, const int* in_sizes, int n_in,
                              void* d_out, int out_size)
{
    const float* x    = (const float*)d_in[0];
    const float* Wq   = (const float*)d_in[1];
    const float* bq   = (const float*)d_in[2];
    const float* Wk   = (const float*)d_in[3];
    const float* bk   = (const float*)d_in[4];
    const float* Wv   = (const float*)d_in[5];
    const float* bv   = (const float*)d_in[6];
    const float* ln1g = (const float*)d_in[7];
    const float* ln1b = (const float*)d_in[8];
    const float* Wf1  = (const float*)d_in[9];
    const float* bf1  = (const float*)d_in[10];
    const float* Wf2  = (const float*)d_in[11];
    const float* bf2  = (const float*)d_in[12];
    const float* ln2g = (const float*)d_in[13];
    const float* ln2b = (const float*)d_in[14];
    (void)in_sizes; (void)n_in; (void)out_size;

    float* out       = (float*)d_out;                    /* [16384,512]   */
    float* out_score = out + (size_t)MROWS * DMODEL;     /* [16,8192,257] */

    float *pxt, *pwq, *pwk, *pwv, *pw1, *pw2;
    cudaGetSymbolAddress((void**)&pxt, g_xt);
    cudaGetSymbolAddress((void**)&pwq, g_wq);
    cudaGetSymbolAddress((void**)&pwk, g_wk);
    cudaGetSymbolAddress((void**)&pwv, g_wv);
    cudaGetSymbolAddress((void**)&pw1, g_w1);
    cudaGetSymbolAddress((void**)&pw2, g_w2);

    /* 0. pre-round operands to tf32 */
    cvt_copy<<<(MROWS*DMODEL/4 + 255)/256, 256>>>(x,   pxt, MROWS*DMODEL/4);
    cvt_copy<<<(DMODEL*DMODEL/4 + 255)/256, 256>>>(Wq, pwq, DMODEL*DMODEL/4);
    cvt_copy<<<(DMODEL*DMODEL/4 + 255)/256, 256>>>(Wk, pwk, DMODEL*DMODEL/4);
    cvt_copy<<<(DMODEL*DMODEL/4 + 255)/256, 256>>>(Wv, pwv, DMODEL*DMODEL/4);
    cvt_copy<<<(DMODEL*DHID/4 + 255)/256, 256>>>(Wf1, pw1, DMODEL*DHID/4);
    cvt_copy<<<(DHID*DMODEL/4 + 255)/256, 256>>>(Wf2, pw2, DHID*DMODEL/4);

    /* 1. QKV projections */
    mma_gemm<0><<<dim3(DMODEL/128, MROWS/128, 3), 256>>>(bq, bk, bv);
    /* 2. attention (tensor-core) */
    attn_kernel<<<dim3(SEQ/64, BH), 256>>>(out_score);
    /* 3. normalize band */
    band_norm<<<BH*SEQ, 128>>>(out_score);
    /* 4. h = tf32(LN(attn + x)) */
    ln_res<0><<<MROWS, 128>>>(x, ln1g, ln1b, nullptr);
    /* 5. ff1 = tf32(relu(h @ Wf1 + bf1)) */
    mma_gemm<1><<<dim3(DHID/128, MROWS/128), 256>>>(bf1, nullptr, nullptr);
    /* 6. ff2 = ff1 @ Wf2 + bf2 */
    mma_gemm<2><<<dim3(DMODEL/128, MROWS/128), 256>>>(bf2, nullptr, nullptr);
    /* 7. out = LN(ff2 + h) */
    ln_res<1><<<MROWS, 128>>>(x, ln2g, ln2b, out);
}

// round 14
// speedup vs baseline: 1.2290x; 1.0038x over previous
#include <cuda_runtime.h>
#include <math.h>
#include <stdint.h>

#define BATCH  2
#define SEQ    8192
#define DMODEL 512
#define NH     8
#define HD     64
#define DHID   2048
#define BH     (BATCH*NH)     /* 16    */
#define MROWS  (BATCH*SEQ)    /* 16384 */

/* ---------------- scratch: __device__ globals only ---------------- */
__device__ float g_q[BH*SEQ*HD];
__device__ float g_k[BH*SEQ*HD];
__device__ float g_v[BH*SEQ*HD];
__device__ float g_attn[MROWS*DMODEL];
__device__ float g_h[MROWS*DMODEL];      /* stored tf32-rounded */
__device__ float g_ff1[MROWS*DHID];      /* stored tf32-rounded */
__device__ float g_ff2[MROWS*DMODEL];
__device__ float g_inv[BH*SEQ];
/* pre-rounded tf32 operand buffers */
__device__ float g_xt[MROWS*DMODEL];
__device__ float g_wq[DMODEL*DMODEL];
__device__ float g_wk[DMODEL*DMODEL];
__device__ float g_wv[DMODEL*DMODEL];
__device__ float g_w1[DMODEL*DHID];
__device__ float g_w2[DHID*DMODEL];

__device__ __forceinline__ uint32_t smem_u32(const void* p) {
    uint32_t a;
    asm("{ .reg .u64 t; cvta.to.shared.u64 t, %1; cvt.u32.u64 %0, t; }"
        : "=r"(a) : "l"(p));
    return a;
}
__device__ __forceinline__ uint32_t cvt_tf32(float x) {
    uint32_t r; asm("cvt.rna.tf32.f32 %0, %1;" : "=r"(r) : "f"(x)); return r;
}
__device__ __forceinline__ float round_tf32(float x) {
    return __uint_as_float(cvt_tf32(x));
}
__device__ __forceinline__ void mma_tf32(
    float& c0, float& c1, float& c2, float& c3,
    uint32_t a0, uint32_t a1, uint32_t a2, uint32_t a3,
    uint32_t b0, uint32_t b1)
{
    asm volatile(
        "mma.sync.aligned.m16n8k8.row.col.f32.tf32.tf32.f32 "
        "{%0,%1,%2,%3}, {%4,%5,%6,%7}, {%8,%9}, {%0,%1,%2,%3};"
        : "+f"(c0), "+f"(c1), "+f"(c2), "+f"(c3)
        : "r"(a0), "r"(a1), "r"(a2), "r"(a3), "r"(b0), "r"(b1));
}
__device__ __forceinline__ void cp16(uint32_t dst, const void* src) {
    asm volatile("cp.async.cg.shared.global [%0], [%1], 16;"
                 :: "r"(dst), "l"(src));
}
#define CP_COMMIT()  asm volatile("cp.async.commit_group;" ::: "memory")
#define CP_WAIT2()   asm volatile("cp.async.wait_group 2;" ::: "memory")

#define PA 20
#define PB 136
#define BK 16
#define STAGES 4
#define STG_FLOATS (128*PA + BK*PB)            /* 4736 floats            */
#define GEMM_SMEM  (STAGES*STG_FLOATS*4)       /* 75776 bytes            */

/* ================= tf32 pre-round copy kernel ================= */
__global__ void __launch_bounds__(256) cvt_copy(
    const float* __restrict__ src, float* __restrict__ dst, int n4)
{
    int i = blockIdx.x * 256 + threadIdx.x;
    if (i < n4) {
        float4 v = ((const float4*)src)[i];
        v.x = round_tf32(v.x); v.y = round_tf32(v.y);
        v.z = round_tf32(v.z); v.w = round_tf32(v.w);
        ((float4*)dst)[i] = v;
    }
}

/* =================================================================
 * tf32 warp-MMA GEMM, tile 128x128x16, 256 thr (2x4 warps, 64x32 warp
 * tile), 4-stage cp.async ring (3 chunks in flight), 1 sync per chunk,
 * operands pre-rounded to tf32 in gmem.
 * MODE 0: QKV   MODE 1: FFN1   MODE 2: FFN2
 * ================================================================= */
template<int MODE>
__global__ void __launch_bounds__(256) mma_gemm(
    const float* __restrict__ b0p,
    const float* __restrict__ b1p,
    const float* __restrict__ b2p)
{
    constexpr int N = (MODE == 1) ? DHID : DMODEL;
    constexpr int K = (MODE == 2) ? DHID : DMODEL;
    constexpr int NIT = K / BK;

    extern __shared__ uint32_t smp[];
    const uint32_t sbase = smem_u32(smp);

    const int tid  = threadIdx.x;
    const int wid  = tid >> 5;
    const int lane = tid & 31;
    const int gr   = lane >> 2;
    const int tg   = lane & 3;
    const int wm   = wid & 1;
    const int wn   = wid >> 1;
    const int m0   = blockIdx.y * 128;
    const int n0   = blockIdx.x * 128;

    const float* Ag; const float* Bg; const float* bias;
    if (MODE == 0) {
        Ag = g_xt;
        if (blockIdx.z == 0)      { Bg = g_wq; bias = b0p; }
        else if (blockIdx.z == 1) { Bg = g_wk; bias = b1p; }
        else                      { Bg = g_wv; bias = b2p; }
    } else if (MODE == 1) { Ag = g_h;   Bg = g_w1; bias = b0p; }
    else                  { Ag = g_ff1; Bg = g_w2; bias = b0p; }

    float acc[4][4][4];
#pragma unroll
    for (int i = 0; i < 4; i++)
#pragma unroll
        for (int j = 0; j < 4; j++)
#pragma unroll
            for (int r = 0; r < 4; r++) acc[i][j][r] = 0.f;

    const int arow0 = tid >> 2,  ac4 = (tid & 3);
    const int brow0 = tid >> 5,  bc4 = (tid & 31);

#define ISSUE(cc, ss)                                                        \
    do {                                                                     \
        const int _k0 = (cc) * BK;                                           \
        const uint32_t _ab = sbase + (uint32_t)((ss) * STG_FLOATS) * 4u;     \
        const uint32_t _bb = _ab + (uint32_t)(128 * PA) * 4u;                \
        cp16(_ab + (uint32_t)(arow0 * PA + ac4 * 4) * 4u,                    \
             Ag + (size_t)(m0 + arow0) * K + _k0 + ac4 * 4);                 \
        cp16(_ab + (uint32_t)((arow0 + 64) * PA + ac4 * 4) * 4u,             \
             Ag + (size_t)(m0 + arow0 + 64) * K + _k0 + ac4 * 4);            \
        cp16(_bb + (uint32_t)(brow0 * PB + bc4 * 4) * 4u,                    \
             Bg + (size_t)(_k0 + brow0) * N + n0 + bc4 * 4);                 \
        cp16(_bb + (uint32_t)((brow0 + 8) * PB + bc4 * 4) * 4u,              \
             Bg + (size_t)(_k0 + brow0 + 8) * N + n0 + bc4 * 4);             \
    } while (0)

    /* prologue: chunks 0..2 into stages 0..2 */
#pragma unroll
    for (int s = 0; s < STAGES - 1; s++) {
        ISSUE(s, s);
        CP_COMMIT();
    }

    for (int c = 0; c < NIT; c++) {
        CP_WAIT2();                  /* retire group c (keep c+1,c+2)     */
        __syncthreads();             /* visibility + stage-reuse fence    */
        if (c + STAGES - 1 < NIT)
            ISSUE(c + STAGES - 1, (c + STAGES - 1) & (STAGES - 1));
        CP_COMMIT();                 /* one group per iter (maybe empty)  */

        const uint32_t* sA = smp + (c & (STAGES - 1)) * STG_FLOATS;
        const uint32_t* sB = sA + 128 * PA;

#pragma unroll
        for (int kf = 0; kf < 2; kf++) {
            uint32_t a[4][4], b[4][2];
#pragma unroll
            for (int mf = 0; mf < 4; mf++) {
                const uint32_t* ap = &sA[(wm*64 + mf*16 + gr) * PA + kf*8 + tg];
                a[mf][0] = ap[0];
                a[mf][1] = ap[8 * PA];
                a[mf][2] = ap[4];
                a[mf][3] = ap[8 * PA + 4];
            }
#pragma unroll
            for (int nf = 0; nf < 4; nf++) {
                const uint32_t* bp = &sB[(kf*8 + tg) * PB + wn*32 + nf*8 + gr];
                b[nf][0] = bp[0];
                b[nf][1] = bp[4 * PB];
            }
#pragma unroll
            for (int mf = 0; mf < 4; mf++)
#pragma unroll
                for (int nf = 0; nf < 4; nf++)
                    mma_tf32(acc[mf][nf][0], acc[mf][nf][1],
                             acc[mf][nf][2], acc[mf][nf][3],
                             a[mf][0], a[mf][1], a[mf][2], a[mf][3],
                             b[nf][0], b[nf][1]);
        }
    }
#undef ISSUE

    /* ---------------- epilogue ---------------- */
#pragma unroll
    for (int mf = 0; mf < 4; mf++) {
#pragma unroll
        for (int nf = 0; nf < 4; nf++) {
            int mrow = m0 + wm*64 + mf*16 + gr;
            int ncol = n0 + wn*32 + nf*8 + 2*tg;
            float bx = bias[ncol], by = bias[ncol+1];
            float2 r0 = make_float2(acc[mf][nf][0] + bx, acc[mf][nf][1] + by);
            float2 r1 = make_float2(acc[mf][nf][2] + bx, acc[mf][nf][3] + by);
            if (MODE == 0) {
                const float scale = (blockIdx.z == 0) ? 0.125f : 1.f;
                float* outp = (blockIdx.z == 0) ? g_q
                            : ((blockIdx.z == 1) ? g_k : g_v);
                r0.x *= scale; r0.y *= scale; r1.x *= scale; r1.y *= scale;
                int h = ncol >> 6, d = ncol & 63;
                {
                    int bb = mrow >> 13, s = mrow & (SEQ-1);
                    *(float2*)&outp[(((size_t)bb*NH + h)*SEQ + s)*HD + d] = r0;
                }
                {
                    int m2 = mrow + 8;
                    int bb = m2 >> 13, s = m2 & (SEQ-1);
                    *(float2*)&outp[(((size_t)bb*NH + h)*SEQ + s)*HD + d] = r1;
                }
            } else {
                float* Cg = (MODE == 1) ? g_ff1 : g_ff2;
                if (MODE == 1) {
                    r0.x = round_tf32(fmaxf(r0.x, 0.f));
                    r0.y = round_tf32(fmaxf(r0.y, 0.f));
                    r1.x = round_tf32(fmaxf(r1.x, 0.f));
                    r1.y = round_tf32(fmaxf(r1.y, 0.f));
                }
                *(float2*)&Cg[(size_t)mrow * N + ncol] = r0;
                *(float2*)&Cg[(size_t)(mrow+8) * N + ncol] = r1;
            }
        }
    }
}

/* =================================================================
 * Tensor-core sliding-window attention (unchanged from R12 PASS)
 * ================================================================= */
__global__ void __launch_bounds__(256) attn_kernel(float* __restrict__ out_score)
{
    __shared__ uint32_t qs[64*68];
    __shared__ uint32_t ks[32*68];
    __shared__ uint32_t vs[32*72];
    __shared__ uint32_t pt[64*36];
    __shared__ float red[4][64];
    __shared__ float invs[64];

    const int tid = threadIdx.x;
    const int bh  = blockIdx.y;
    const int q0  = blockIdx.x * 64;
    const float* qg = g_q + (size_t)bh * SEQ * HD;
    const float* kg = g_k + (size_t)bh * SEQ * HD;
    const float* vg = g_v + (size_t)bh * SEQ * HD;

    for (int i = tid; i < 64 * 16; i += 256) {
        int row = i >> 4;
        int c4  = (i & 15) * 4;
        float4 v = *(const float4*)(qg + (size_t)(q0 + row) * HD + c4);
        uint4 t;
        t.x = cvt_tf32(v.x); t.y = cvt_tf32(v.y);
        t.z = cvt_tf32(v.z); t.w = cvt_tf32(v.w);
        *(uint4*)&qs[row*68 + c4] = t;
    }

    const int lane = tid & 31;
    const int wid  = tid >> 5;
    const int gr   = lane >> 2;
    const int tg   = lane & 3;
    const int wm   = wid & 1;
    const int wn   = wid >> 1;

    float accO[2][2][4];
#pragma unroll
    for (int i = 0; i < 2; i++)
#pragma unroll
        for (int j = 0; j < 2; j++)
#pragma unroll
            for (int r = 0; r < 4; r++) accO[i][j][r] = 0.f;
    float psum[4] = {0.f, 0.f, 0.f, 0.f};

    for (int t = 0; t < 10; t++) {
        __syncthreads();
        const int gbase = q0 - 128 + t * 32;
        for (int i = tid; i < 32 * 16; i += 256) {
            int row = i >> 4;
            int c4  = (i & 15) * 4;
            int g = gbase + row;
            float4 kk = make_float4(0.f,0.f,0.f,0.f);
            float4 vv = make_float4(0.f,0.f,0.f,0.f);
            if (g >= 0 && g < SEQ) {
                kk = *(const float4*)(kg + (size_t)g * HD + c4);
                vv = *(const float4*)(vg + (size_t)g * HD + c4);
            }
            uint4 tk, tv;
            tk.x = cvt_tf32(kk.x); tk.y = cvt_tf32(kk.y);
            tk.z = cvt_tf32(kk.z); tk.w = cvt_tf32(kk.w);
            tv.x = cvt_tf32(vv.x); tv.y = cvt_tf32(vv.y);
            tv.z = cvt_tf32(vv.z); tv.w = cvt_tf32(vv.w);
            *(uint4*)&ks[row*68 + c4] = tk;
            *(uint4*)&vs[row*72 + c4] = tv;
        }
        __syncthreads();

        float sc[2][4];
#pragma unroll
        for (int i = 0; i < 2; i++)
#pragma unroll
            for (int r = 0; r < 4; r++) sc[i][r] = 0.f;
#pragma unroll
        for (int kf = 0; kf < 8; kf++) {
            uint32_t a[2][4], b[2];
#pragma unroll
            for (int mf = 0; mf < 2; mf++) {
                const uint32_t* ap = &qs[(wm*32 + mf*16 + gr)*68 + kf*8 + tg];
                a[mf][0] = ap[0];
                a[mf][1] = ap[8*68];
                a[mf][2] = ap[4];
                a[mf][3] = ap[8*68 + 4];
            }
            const uint32_t* bp = &ks[(wn*8 + gr)*68 + kf*8 + tg];
            b[0] = bp[0];
            b[1] = bp[4];
#pragma unroll
            for (int mf = 0; mf < 2; mf++)
                mma_tf32(sc[mf][0], sc[mf][1], sc[mf][2], sc[mf][3],
                         a[mf][0], a[mf][1], a[mf][2], a[mf][3],
                         b[0], b[1]);
        }

#pragma unroll
        for (int mf = 0; mf < 2; mf++) {
            const int rb = wm*32 + mf*16 + gr;
            const int n0 = wn*8 + 2*tg;
#pragma unroll
            for (int h = 0; h < 2; h++) {
                const int r = rb + h*8;
#pragma unroll
                for (int cc = 0; cc < 2; cc++) {
                    const int kloc = n0 + cc;
                    const int jb = t*32 + kloc - r;
                    const int g  = gbase + kloc;
                    float e = 0.f;
                    if (jb >= 0 && jb <= 256 && g >= 0 && g < SEQ)
                        e = expf(sc[mf][h*2 + cc]);
                    pt[r*36 + kloc] = cvt_tf32(e);
                    psum[mf*2 + h] += e;
                }
            }
        }
        __syncthreads();

        {
            float* osc = out_score + ((size_t)bh * SEQ + q0) * 257;
#pragma unroll
            for (int i = tid; i < 64 * 32; i += 256) {
                int q = i >> 5;
                int k = i & 31;
                int jb = t*32 + k - q;
                if (jb >= 0 && jb <= 256)
                    osc[(size_t)q * 257 + jb] = __uint_as_float(pt[q*36 + k]);
            }
        }

#pragma unroll
        for (int kf = 0; kf < 4; kf++) {
            uint32_t a[2][4], b[2][2];
#pragma unroll
            for (int mf = 0; mf < 2; mf++) {
                const uint32_t* ap = &pt[(wm*32 + mf*16 + gr)*36 + kf*8 + tg];
                a[mf][0] = ap[0];
                a[mf][1] = ap[8*36];
                a[mf][2] = ap[4];
                a[mf][3] = ap[8*36 + 4];
            }
#pragma unroll
            for (int nf = 0; nf < 2; nf++) {
                const uint32_t* bp = &vs[(kf*8 + tg)*72 + wn*16 + nf*8 + gr];
                b[nf][0] = bp[0];
                b[nf][1] = bp[4*72];
            }
#pragma unroll
            for (int mf = 0; mf < 2; mf++)
#pragma unroll
                for (int nf = 0; nf < 2; nf++)
                    mma_tf32(accO[mf][nf][0], accO[mf][nf][1],
                             accO[mf][nf][2], accO[mf][nf][3],
                             a[mf][0], a[mf][1], a[mf][2], a[mf][3],
                             b[nf][0], b[nf][1]);
        }
    }

#pragma unroll
    for (int j = 0; j < 4; j++) {
        psum[j] += __shfl_xor_sync(0xFFFFFFFFu, psum[j], 1);
        psum[j] += __shfl_xor_sync(0xFFFFFFFFu, psum[j], 2);
    }
    if (tg == 0) {
#pragma unroll
        for (int j = 0; j < 4; j++) {
            int q = wm*32 + (j >> 1)*16 + (j & 1)*8 + gr;
            red[wn][q] = psum[j];
        }
    }
    __syncthreads();
    if (tid < 64) {
        float s = red[0][tid] + red[1][tid] + red[2][tid] + red[3][tid];
        float iv = 1.f / s;
        invs[tid] = iv;
        g_inv[(size_t)bh * SEQ + q0 + tid] = iv;
    }
    __syncthreads();

    const int bb = bh >> 3;
    const int hh = bh & 7;
#pragma unroll
    for (int mf = 0; mf < 2; mf++) {
#pragma unroll
        for (int nf = 0; nf < 2; nf++) {
            int r  = wm*32 + mf*16 + gr;
            int d0 = wn*16 + nf*8 + 2*tg;
            float iv0 = invs[r];
            float iv1 = invs[r + 8];
            float2 o0 = make_float2(accO[mf][nf][0]*iv0, accO[mf][nf][1]*iv0);
            float2 o1 = make_float2(accO[mf][nf][2]*iv1, accO[mf][nf][3]*iv1);
            *(float2*)&g_attn[((size_t)bb*SEQ + q0 + r)     * DMODEL + hh*HD + d0] = o0;
            *(float2*)&g_attn[((size_t)bb*SEQ + q0 + r + 8) * DMODEL + hh*HD + d0] = o1;
        }
    }
}

__global__ void __launch_bounds__(128) band_norm(float* __restrict__ out_score)
{
    const int row = blockIdx.x;
    const float iv = g_inv[row];
    float* p = out_score + (size_t)row * 257;
    for (int t = threadIdx.x; t < 257; t += 128)
        p[t] *= iv;
}

template<int MODE>
__global__ void __launch_bounds__(128) ln_res(
    const float* __restrict__ xb,
    const float* __restrict__ gam, const float* __restrict__ bet,
    float* __restrict__ outp)
{
    const float* a = (MODE == 0) ? g_attn : g_ff2;
    const float* b = (MODE == 0) ? xb     : g_h;
    float* out     = (MODE == 0) ? g_h    : outp;

    __shared__ float sred[2][4];
    const int row = blockIdx.x;
    const int tid = threadIdx.x;
    const float4 va = ((const float4*)(a + (size_t)row * DMODEL))[tid];
    const float4 vb = ((const float4*)(b + (size_t)row * DMODEL))[tid];
    float4 v = make_float4(va.x+vb.x, va.y+vb.y, va.z+vb.z, va.w+vb.w);
    float s  = v.x + v.y + v.z + v.w;
    float sq = v.x*v.x + v.y*v.y + v.z*v.z + v.w*v.w;
#pragma unroll
    for (int o = 16; o > 0; o >>= 1) {
        s  += __shfl_down_sync(0xFFFFFFFFu, s,  o);
        sq += __shfl_down_sync(0xFFFFFFFFu, sq, o);
    }
    if ((tid & 31) == 0) { sred[0][tid >> 5] = s; sred[1][tid >> 5] = sq; }
    __syncthreads();
    s  = sred[0][0] + sred[0][1] + sred[0][2] + sred[0][3];
    sq = sred[1][0] + sred[1][1] + sred[1][2] + sred[1][3];
    float mean = s * (1.f / DMODEL);
    float var  = sq * (1.f / DMODEL) - mean * mean;
    float rs   = rsqrtf(var + 1e-5f);
    float4 g4 = ((const float4*)gam)[tid];
    float4 b4 = ((const float4*)bet)[tid];
    float4 r;
    r.x = (v.x - mean) * rs * g4.x + b4.x;
    r.y = (v.y - mean) * rs * g4.y + b4.y;
    r.z = (v.z - mean) * rs * g4.z + b4.z;
    r.w = (v.w - mean) * rs * g4.w + b4.w;
    if (MODE == 0) {
        r.x = round_tf32(r.x); r.y = round_tf32(r.y);
        r.z = round_tf32(r.z); r.w = round_tf32(r.w);
    }
    ((float4*)(out + (size_t)row * DMODEL))[tid] = r;
}

/* ================================================================= */
extern "C" void kernel_launch(void* const* d_in, const int* in_sizes, int n_in,
                              void* d_out, int out_size)
{
    const float* x    = (const float*)d_in[0];
    const float* Wq   = (const float*)d_in[1];
    const float* bq   = (const float*)d_in[2];
    const float* Wk   = (const float*)d_in[3];
    const float* bk   = (const float*)d_in[4];
    const float* Wv   = (const float*)d_in[5];
    const float* bv   = (const float*)d_in[6];
    const float* ln1g = (const float*)d_in[7];
    const float* ln1b = (const float*)d_in[8];
    const float* Wf1  = (const float*)d_in[9];
    const float* bf1  = (const float*)d_in[10];
    const float* Wf2  = (const float*)d_in[11];
    const float* bf2  = (const float*)d_in[12];
    const float* ln2g = (const float*)d_in[13];
    const float* ln2b = (const float*)d_in[14];
    (void)in_sizes; (void)n_in; (void)out_size;

    float* out       = (float*)d_out;                    /* [16384,512]   */
    float* out_score = out + (size_t)MROWS * DMODEL;     /* [16,8192,257] */

    float *pxt, *pwq, *pwk, *pwv, *pw1, *pw2;
    cudaGetSymbolAddress((void**)&pxt, g_xt);
    cudaGetSymbolAddress((void**)&pwq, g_wq);
    cudaGetSymbolAddress((void**)&pwk, g_wk);
    cudaGetSymbolAddress((void**)&pwv, g_wv);
    cudaGetSymbolAddress((void**)&pw1, g_w1);
    cudaGetSymbolAddress((void**)&pw2, g_w2);

    cudaFuncSetAttribute(mma_gemm<0>, cudaFuncAttributeMaxDynamicSharedMemorySize, GEMM_SMEM);
    cudaFuncSetAttribute(mma_gemm<1>, cudaFuncAttributeMaxDynamicSharedMemorySize, GEMM_SMEM);
    cudaFuncSetAttribute(mma_gemm<2>, cudaFuncAttributeMaxDynamicSharedMemorySize, GEMM_SMEM);

    /* 0. pre-round operands to tf32 */
    cvt_copy<<<(MROWS*DMODEL/4 + 255)/256, 256>>>(x,   pxt, MROWS*DMODEL/4);
    cvt_copy<<<(DMODEL*DMODEL/4 + 255)/256, 256>>>(Wq, pwq, DMODEL*DMODEL/4);
    cvt_copy<<<(DMODEL*DMODEL/4 + 255)/256, 256>>>(Wk, pwk, DMODEL*DMODEL/4);
    cvt_copy<<<(DMODEL*DMODEL/4 + 255)/256, 256>>>(Wv, pwv, DMODEL*DMODEL/4);
    cvt_copy<<<(DMODEL*DHID/4 + 255)/256, 256>>>(Wf1, pw1, DMODEL*DHID/4);
    cvt_copy<<<(DHID*DMODEL/4 + 255)/256, 256>>>(Wf2, pw2, DHID*DMODEL/4);

    /* 1. QKV projections */
    mma_gemm<0><<<dim3(DMODEL/128, MROWS/128, 3), 256, GEMM_SMEM>>>(bq, bk, bv);
    /* 2. attention (tensor-core) */
    attn_kernel<<<dim3(SEQ/64, BH), 256>>>(out_score);
    /* 3. normalize band */
    band_norm<<<BH*SEQ, 128>>>(out_score);
    /* 4. h = tf32(LN(attn + x)) */
    ln_res<0><<<MROWS, 128>>>(x, ln1g, ln1b, nullptr);
    /* 5. ff1 = tf32(relu(h @ Wf1 + bf1)) */
    mma_gemm<1><<<dim3(DHID/128, MROWS/128), 256, GEMM_SMEM>>>(bf1, nullptr, nullptr);
    /* 6. ff2 = ff1 @ Wf2 + bf2 */
    mma_gemm<2><<<dim3(DMODEL/128, MROWS/128), 256, GEMM_SMEM>>>(bf2, nullptr, nullptr);
    /* 7. out = LN(ff2 + h) */
    ln_res<1><<<MROWS, 128>>>(x, ln2g, ln2b, out);
}

// round 16
// speedup vs baseline: 1.6727x; 1.3611x over previous
#include <cuda_runtime.h>
#include <cuda_fp16.h>
#include <math.h>
#include <stdint.h>

#define BATCH  2
#define SEQ    8192
#define DMODEL 512
#define NH     8
#define HD     64
#define DHID   2048
#define BH     (BATCH*NH)     /* 16    */
#define MROWS  (BATCH*SEQ)    /* 16384 */

/* ---------------- scratch: __device__ globals only ---------------- */
__device__ float g_q[BH*SEQ*HD];
__device__ float g_k[BH*SEQ*HD];
__device__ float g_v[BH*SEQ*HD];
__device__ float g_attn[MROWS*DMODEL];
__device__ float g_h[MROWS*DMODEL];          /* fp32 (residual path)   */
__device__ float g_ff2[MROWS*DMODEL];
__device__ float g_inv[BH*SEQ];
/* packed-half operand buffers (uint32 = half2) */
__device__ uint32_t g_xh  [MROWS*DMODEL/2];  /* A of QKV  */
__device__ uint32_t g_hh  [MROWS*DMODEL/2];  /* A of FFN1 */
__device__ uint32_t g_ff1h[MROWS*DHID/2];    /* A of FFN2 */
__device__ uint32_t g_wqh [DMODEL/2*DMODEL];
__device__ uint32_t g_wkh [DMODEL/2*DMODEL];
__device__ uint32_t g_wvh [DMODEL/2*DMODEL];
__device__ uint32_t g_w1h [DMODEL/2*DHID];
__device__ uint32_t g_w2h [DHID/2*DMODEL];

__device__ __forceinline__ uint32_t smem_u32(const void* p) {
    uint32_t a;
    asm("{ .reg .u64 t; cvta.to.shared.u64 t, %1; cvt.u32.u64 %0, t; }"
        : "=r"(a) : "l"(p));
    return a;
}
__device__ __forceinline__ uint32_t cvt_tf32(float x) {
    uint32_t r; asm("cvt.rna.tf32.f32 %0, %1;" : "=r"(r) : "f"(x)); return r;
}
__device__ __forceinline__ uint32_t pack_h2(float a, float b) {
    __half2 h = __floats2half2_rn(a, b);
    return reinterpret_cast<uint32_t&>(h);
}
__device__ __forceinline__ void mma_tf32(
    float& c0, float& c1, float& c2, float& c3,
    uint32_t a0, uint32_t a1, uint32_t a2, uint32_t a3,
    uint32_t b0, uint32_t b1)
{
    asm volatile(
        "mma.sync.aligned.m16n8k8.row.col.f32.tf32.tf32.f32 "
        "{%0,%1,%2,%3}, {%4,%5,%6,%7}, {%8,%9}, {%0,%1,%2,%3};"
        : "+f"(c0), "+f"(c1), "+f"(c2), "+f"(c3)
        : "r"(a0), "r"(a1), "r"(a2), "r"(a3), "r"(b0), "r"(b1));
}
__device__ __forceinline__ void mma_f16(
    float& c0, float& c1, float& c2, float& c3,
    uint32_t a0, uint32_t a1, uint32_t a2, uint32_t a3,
    uint32_t b0, uint32_t b1)
{
    asm volatile(
        "mma.sync.aligned.m16n8k16.row.col.f32.f16.f16.f32 "
        "{%0,%1,%2,%3}, {%4,%5,%6,%7}, {%8,%9}, {%0,%1,%2,%3};"
        : "+f"(c0), "+f"(c1), "+f"(c2), "+f"(c3)
        : "r"(a0), "r"(a1), "r"(a2), "r"(a3), "r"(b0), "r"(b1));
}
__device__ __forceinline__ void cp16(uint32_t dst, const void* src) {
    asm volatile("cp.async.cg.shared.global [%0], [%1], 16;"
                 :: "r"(dst), "l"(src));
}
#define CP_COMMIT()  asm volatile("cp.async.commit_group;" ::: "memory")
#define CP_WAIT2()   asm volatile("cp.async.wait_group 2;" ::: "memory")

#define PAH 20     /* A word pitch: banks (20*gr+tg)%32 distinct         */
#define PBH 136    /* B word pitch: banks (8*tg+gr)%32 distinct          */
#define BKW 16     /* K-words per chunk (= 32 halves = K32)              */
#define STAGES 4
#define STG_WORDS (128*PAH + BKW*PBH)          /* 4736 words             */
#define GEMM_SMEM (STAGES*STG_WORDS*4)         /* 75776 bytes            */

/* ================= prep kernels ================= */
/* A-pack: contiguous float pairs -> half2 words */
__global__ void __launch_bounds__(256) pack_a(
    const float* __restrict__ src, uint32_t* __restrict__ dst, int nw)
{
    int i = blockIdx.x * 256 + threadIdx.x;
    if (i < nw) {
        float2 v = ((const float2*)src)[i];
        dst[i] = pack_h2(v.x, v.y);
    }
}
/* B-pack: word(kk,n) = {W[2kk][n], W[2kk+1][n]} */
__global__ void __launch_bounds__(256) pack_b(
    const float* __restrict__ W, uint32_t* __restrict__ dst, int N, int nw)
{
    int i = blockIdx.x * 256 + threadIdx.x;
    if (i < nw) {
        int kk = i / N, n = i - kk * N;
        dst[i] = pack_h2(W[(size_t)(2*kk) * N + n],
                         W[(size_t)(2*kk+1) * N + n]);
    }
}

/* =================================================================
 * fp16 warp-MMA GEMM (m16n8k16), tile 128x128x32, 256 thr
 * (2x4 warps, 64x32 warp tile), 4-stage cp.async ring.
 * MODE 0: QKV (z selects)  MODE 1: FFN1  MODE 2: FFN2
 * ================================================================= */
template<int MODE>
__global__ void __launch_bounds__(256) mma_gemm(
    const float* __restrict__ b0p,
    const float* __restrict__ b1p,
    const float* __restrict__ b2p)
{
    constexpr int N  = (MODE == 1) ? DHID : DMODEL;
    constexpr int K  = (MODE == 2) ? DHID : DMODEL;
    constexpr int K2 = K / 2;                 /* words per A row        */
    constexpr int NIT = K / 32;               /* chunks of 32 halves    */

    extern __shared__ uint32_t smp[];
    const uint32_t sbase = smem_u32(smp);

    const int tid  = threadIdx.x;
    const int wid  = tid >> 5;
    const int lane = tid & 31;
    const int gr   = lane >> 2;
    const int tg   = lane & 3;
    const int wm   = wid & 1;
    const int wn   = wid >> 1;
    const int m0   = blockIdx.y * 128;
    const int n0   = blockIdx.x * 128;

    const uint32_t* Ah; const uint32_t* Bh; const float* bias;
    if (MODE == 0) {
        Ah = g_xh;
        if (blockIdx.z == 0)      { Bh = g_wqh; bias = b0p; }
        else if (blockIdx.z == 1) { Bh = g_wkh; bias = b1p; }
        else                      { Bh = g_wvh; bias = b2p; }
    } else if (MODE == 1) { Ah = g_hh;   Bh = g_w1h; bias = b0p; }
    else                  { Ah = g_ff1h; Bh = g_w2h; bias = b0p; }

    float acc[4][4][4];
#pragma unroll
    for (int i = 0; i < 4; i++)
#pragma unroll
        for (int j = 0; j < 4; j++)
#pragma unroll
            for (int r = 0; r < 4; r++) acc[i][j][r] = 0.f;

    const int arow = tid >> 1, aw0 = (tid & 1) * 8;   /* A: 2 cp16/thr */
    const int brow = tid >> 4, bw0 = (tid & 15) * 8;  /* B: 2 cp16/thr */

#define ISSUE(cc, ss)                                                        \
    do {                                                                     \
        const int _kw = (cc) * BKW;                                          \
        const uint32_t _ab = sbase + (uint32_t)((ss) * STG_WORDS) * 4u;      \
        const uint32_t _bb = _ab + (uint32_t)(128 * PAH) * 4u;               \
        cp16(_ab + (uint32_t)(arow * PAH + aw0) * 4u,                        \
             Ah + (size_t)(m0 + arow) * K2 + _kw + aw0);                     \
        cp16(_ab + (uint32_t)(arow * PAH + aw0 + 4) * 4u,                    \
             Ah + (size_t)(m0 + arow) * K2 + _kw + aw0 + 4);                 \
        cp16(_bb + (uint32_t)(brow * PBH + bw0) * 4u,                        \
             Bh + (size_t)(_kw + brow) * N + n0 + bw0);                      \
        cp16(_bb + (uint32_t)(brow * PBH + bw0 + 4) * 4u,                    \
             Bh + (size_t)(_kw + brow) * N + n0 + bw0 + 4);                  \
    } while (0)

    /* prologue: chunks 0..2 into stages 0..2 */
#pragma unroll
    for (int s = 0; s < STAGES - 1; s++) {
        ISSUE(s, s);
        CP_COMMIT();
    }

    for (int c = 0; c < NIT; c++) {
        CP_WAIT2();
        __syncthreads();
        if (c + STAGES - 1 < NIT)
            ISSUE(c + STAGES - 1, (c + STAGES - 1) & (STAGES - 1));
        CP_COMMIT();

        const uint32_t* sA = smp + (c & (STAGES - 1)) * STG_WORDS;
        const uint32_t* sB = sA + 128 * PAH;

#pragma unroll
        for (int kf = 0; kf < 2; kf++) {
            uint32_t a[4][4], b[4][2];
#pragma unroll
            for (int mf = 0; mf < 4; mf++) {
                const uint32_t* ap = &sA[(wm*64 + mf*16 + gr) * PAH + kf*8 + tg];
                a[mf][0] = ap[0];
                a[mf][1] = ap[8 * PAH];
                a[mf][2] = ap[4];
                a[mf][3] = ap[8 * PAH + 4];
            }
#pragma unroll
            for (int nf = 0; nf < 4; nf++) {
                const uint32_t* bp = &sB[(kf*8 + tg) * PBH + wn*32 + nf*8 + gr];
                b[nf][0] = bp[0];
                b[nf][1] = bp[4 * PBH];
            }
#pragma unroll
            for (int mf = 0; mf < 4; mf++)
#pragma unroll
                for (int nf = 0; nf < 4; nf++)
                    mma_f16(acc[mf][nf][0], acc[mf][nf][1],
                            acc[mf][nf][2], acc[mf][nf][3],
                            a[mf][0], a[mf][1], a[mf][2], a[mf][3],
                            b[nf][0], b[nf][1]);
        }
    }
#undef ISSUE

    /* ---------------- epilogue ---------------- */
#pragma unroll
    for (int mf = 0; mf < 4; mf++) {
#pragma unroll
        for (int nf = 0; nf < 4; nf++) {
            int mrow = m0 + wm*64 + mf*16 + gr;
            int ncol = n0 + wn*32 + nf*8 + 2*tg;
            float bx = bias[ncol], by = bias[ncol+1];
            float2 r0 = make_float2(acc[mf][nf][0] + bx, acc[mf][nf][1] + by);
            float2 r1 = make_float2(acc[mf][nf][2] + bx, acc[mf][nf][3] + by);
            if (MODE == 0) {
                const float scale = (blockIdx.z == 0) ? 0.125f : 1.f;
                float* outp = (blockIdx.z == 0) ? g_q
                            : ((blockIdx.z == 1) ? g_k : g_v);
                r0.x *= scale; r0.y *= scale; r1.x *= scale; r1.y *= scale;
                int h = ncol >> 6, d = ncol & 63;
                {
                    int bb = mrow >> 13, s = mrow & (SEQ-1);
                    *(float2*)&outp[(((size_t)bb*NH + h)*SEQ + s)*HD + d] = r0;
                }
                {
                    int m2 = mrow + 8;
                    int bb = m2 >> 13, s = m2 & (SEQ-1);
                    *(float2*)&outp[(((size_t)bb*NH + h)*SEQ + s)*HD + d] = r1;
                }
            } else if (MODE == 1) {
                /* relu -> packed half2 word (feeds FFN2 A) */
                r0.x = fmaxf(r0.x, 0.f); r0.y = fmaxf(r0.y, 0.f);
                r1.x = fmaxf(r1.x, 0.f); r1.y = fmaxf(r1.y, 0.f);
                g_ff1h[(size_t)mrow * (DHID/2) + (ncol >> 1)]     = pack_h2(r0.x, r0.y);
                g_ff1h[(size_t)(mrow+8) * (DHID/2) + (ncol >> 1)] = pack_h2(r1.x, r1.y);
            } else {
                *(float2*)&g_ff2[(size_t)mrow * DMODEL + ncol] = r0;
                *(float2*)&g_ff2[(size_t)(mrow+8) * DMODEL + ncol] = r1;
            }
        }
    }
}

/* =================================================================
 * Tensor-core sliding-window attention (unchanged from R12 PASS)
 * ================================================================= */
__global__ void __launch_bounds__(256) attn_kernel(float* __restrict__ out_score)
{
    __shared__ uint32_t qs[64*68];
    __shared__ uint32_t ks[32*68];
    __shared__ uint32_t vs[32*72];
    __shared__ uint32_t pt[64*36];
    __shared__ float red[4][64];
    __shared__ float invs[64];

    const int tid = threadIdx.x;
    const int bh  = blockIdx.y;
    const int q0  = blockIdx.x * 64;
    const float* qg = g_q + (size_t)bh * SEQ * HD;
    const float* kg = g_k + (size_t)bh * SEQ * HD;
    const float* vg = g_v + (size_t)bh * SEQ * HD;

    for (int i = tid; i < 64 * 16; i += 256) {
        int row = i >> 4;
        int c4  = (i & 15) * 4;
        float4 v = *(const float4*)(qg + (size_t)(q0 + row) * HD + c4);
        uint4 t;
        t.x = cvt_tf32(v.x); t.y = cvt_tf32(v.y);
        t.z = cvt_tf32(v.z); t.w = cvt_tf32(v.w);
        *(uint4*)&qs[row*68 + c4] = t;
    }

    const int lane = tid & 31;
    const int wid  = tid >> 5;
    const int gr   = lane >> 2;
    const int tg   = lane & 3;
    const int wm   = wid & 1;
    const int wn   = wid >> 1;

    float accO[2][2][4];
#pragma unroll
    for (int i = 0; i < 2; i++)
#pragma unroll
        for (int j = 0; j < 2; j++)
#pragma unroll
            for (int r = 0; r < 4; r++) accO[i][j][r] = 0.f;
    float psum[4] = {0.f, 0.f, 0.f, 0.f};

    for (int t = 0; t < 10; t++) {
        __syncthreads();
        const int gbase = q0 - 128 + t * 32;
        for (int i = tid; i < 32 * 16; i += 256) {
            int row = i >> 4;
            int c4  = (i & 15) * 4;
            int g = gbase + row;
            float4 kk = make_float4(0.f,0.f,0.f,0.f);
            float4 vv = make_float4(0.f,0.f,0.f,0.f);
            if (g >= 0 && g < SEQ) {
                kk = *(const float4*)(kg + (size_t)g * HD + c4);
                vv = *(const float4*)(vg + (size_t)g * HD + c4);
            }
            uint4 tk, tv;
            tk.x = cvt_tf32(kk.x); tk.y = cvt_tf32(kk.y);
            tk.z = cvt_tf32(kk.z); tk.w = cvt_tf32(kk.w);
            tv.x = cvt_tf32(vv.x); tv.y = cvt_tf32(vv.y);
            tv.z = cvt_tf32(vv.z); tv.w = cvt_tf32(vv.w);
            *(uint4*)&ks[row*68 + c4] = tk;
            *(uint4*)&vs[row*72 + c4] = tv;
        }
        __syncthreads();

        float sc[2][4];
#pragma unroll
        for (int i = 0; i < 2; i++)
#pragma unroll
            for (int r = 0; r < 4; r++) sc[i][r] = 0.f;
#pragma unroll
        for (int kf = 0; kf < 8; kf++) {
            uint32_t a[2][4], b[2];
#pragma unroll
            for (int mf = 0; mf < 2; mf++) {
                const uint32_t* ap = &qs[(wm*32 + mf*16 + gr)*68 + kf*8 + tg];
                a[mf][0] = ap[0];
                a[mf][1] = ap[8*68];
                a[mf][2] = ap[4];
                a[mf][3] = ap[8*68 + 4];
            }
            const uint32_t* bp = &ks[(wn*8 + gr)*68 + kf*8 + tg];
            b[0] = bp[0];
            b[1] = bp[4];
#pragma unroll
            for (int mf = 0; mf < 2; mf++)
                mma_tf32(sc[mf][0], sc[mf][1], sc[mf][2], sc[mf][3],
                         a[mf][0], a[mf][1], a[mf][2], a[mf][3],
                         b[0], b[1]);
        }

#pragma unroll
        for (int mf = 0; mf < 2; mf++) {
            const int rb = wm*32 + mf*16 + gr;
            const int n0 = wn*8 + 2*tg;
#pragma unroll
            for (int h = 0; h < 2; h++) {
                const int r = rb + h*8;
#pragma unroll
                for (int cc = 0; cc < 2; cc++) {
                    const int kloc = n0 + cc;
                    const int jb = t*32 + kloc - r;
                    const int g  = gbase + kloc;
                    float e = 0.f;
                    if (jb >= 0 && jb <= 256 && g >= 0 && g < SEQ)
                        e = expf(sc[mf][h*2 + cc]);
                    pt[r*36 + kloc] = cvt_tf32(e);
                    psum[mf*2 + h] += e;
                }
            }
        }
        __syncthreads();

        {
            float* osc = out_score + ((size_t)bh * SEQ + q0) * 257;
#pragma unroll
            for (int i = tid; i < 64 * 32; i += 256) {
                int q = i >> 5;
                int k = i & 31;
                int jb = t*32 + k - q;
                if (jb >= 0 && jb <= 256)
                    osc[(size_t)q * 257 + jb] = __uint_as_float(pt[q*36 + k]);
            }
        }

#pragma unroll
        for (int kf = 0; kf < 4; kf++) {
            uint32_t a[2][4], b[2][2];
#pragma unroll
            for (int mf = 0; mf < 2; mf++) {
                const uint32_t* ap = &pt[(wm*32 + mf*16 + gr)*36 + kf*8 + tg];
                a[mf][0] = ap[0];
                a[mf][1] = ap[8*36];
                a[mf][2] = ap[4];
                a[mf][3] = ap[8*36 + 4];
            }
#pragma unroll
            for (int nf = 0; nf < 2; nf++) {
                const uint32_t* bp = &vs[(kf*8 + tg)*72 + wn*16 + nf*8 + gr];
                b[nf][0] = bp[0];
                b[nf][1] = bp[4*72];
            }
#pragma unroll
            for (int mf = 0; mf < 2; mf++)
#pragma unroll
                for (int nf = 0; nf < 2; nf++)
                    mma_tf32(accO[mf][nf][0], accO[mf][nf][1],
                             accO[mf][nf][2], accO[mf][nf][3],
                             a[mf][0], a[mf][1], a[mf][2], a[mf][3],
                             b[nf][0], b[nf][1]);
        }
    }

#pragma unroll
    for (int j = 0; j < 4; j++) {
        psum[j] += __shfl_xor_sync(0xFFFFFFFFu, psum[j], 1);
        psum[j] += __shfl_xor_sync(0xFFFFFFFFu, psum[j], 2);
    }
    if (tg == 0) {
#pragma unroll
        for (int j = 0; j < 4; j++) {
            int q = wm*32 + (j >> 1)*16 + (j & 1)*8 + gr;
            red[wn][q] = psum[j];
        }
    }
    __syncthreads();
    if (tid < 64) {
        float s = red[0][tid] + red[1][tid] + red[2][tid] + red[3][tid];
        float iv = 1.f / s;
        invs[tid] = iv;
        g_inv[(size_t)bh * SEQ + q0 + tid] = iv;
    }
    __syncthreads();

    const int bb = bh >> 3;
    const int hh = bh & 7;
#pragma unroll
    for (int mf = 0; mf < 2; mf++) {
#pragma unroll
        for (int nf = 0; nf < 2; nf++) {
            int r  = wm*32 + mf*16 + gr;
            int d0 = wn*16 + nf*8 + 2*tg;
            float iv0 = invs[r];
            float iv1 = invs[r + 8];
            float2 o0 = make_float2(accO[mf][nf][0]*iv0, accO[mf][nf][1]*iv0);
            float2 o1 = make_float2(accO[mf][nf][2]*iv1, accO[mf][nf][3]*iv1);
            *(float2*)&g_attn[((size_t)bb*SEQ + q0 + r)     * DMODEL + hh*HD + d0] = o0;
            *(float2*)&g_attn[((size_t)bb*SEQ + q0 + r + 8) * DMODEL + hh*HD + d0] = o1;
        }
    }
}

__global__ void __launch_bounds__(128) band_norm(float* __restrict__ out_score)
{
    const int row = blockIdx.x;
    const float iv = g_inv[row];
    float* p = out_score + (size_t)row * 257;
    for (int t = threadIdx.x; t < 257; t += 128)
        p[t] *= iv;
}

/* =================================================================
 * LayerNorm(a + b): MODE 0: g_h (fp32) + g_hh (half2) = LN(attn + x)
 *                   MODE 1: out = LN(g_ff2 + g_h)
 * ================================================================= */
template<int MODE>
__global__ void __launch_bounds__(128) ln_res(
    const float* __restrict__ xb,
    const float* __restrict__ gam, const float* __restrict__ bet,
    float* __restrict__ outp)
{
    const float* a = (MODE == 0) ? g_attn : g_ff2;
    const float* b = (MODE == 0) ? xb     : g_h;
    float* out     = (MODE == 0) ? g_h    : outp;

    __shared__ float sred[2][4];
    const int row = blockIdx.x;
    const int tid = threadIdx.x;
    const float4 va = ((const float4*)(a + (size_t)row * DMODEL))[tid];
    const float4 vb = ((const float4*)(b + (size_t)row * DMODEL))[tid];
    float4 v = make_float4(va.x+vb.x, va.y+vb.y, va.z+vb.z, va.w+vb.w);
    float s  = v.x + v.y + v.z + v.w;
    float sq = v.x*v.x + v.y*v.y + v.z*v.z + v.w*v.w;
#pragma unroll
    for (int o = 16; o > 0; o >>= 1) {
        s  += __shfl_down_sync(0xFFFFFFFFu, s,  o);
        sq += __shfl_down_sync(0xFFFFFFFFu, sq, o);
    }
    if ((tid & 31) == 0) { sred[0][tid >> 5] = s; sred[1][tid >> 5] = sq; }
    __syncthreads();
    s  = sred[0][0] + sred[0][1] + sred[0][2] + sred[0][3];
    sq = sred[1][0] + sred[1][1] + sred[1][2] + sred[1][3];
    float mean = s * (1.f / DMODEL);
    float var  = sq * (1.f / DMODEL) - mean * mean;
    float rs   = rsqrtf(var + 1e-5f);
    float4 g4 = ((const float4*)gam)[tid];
    float4 b4 = ((const float4*)bet)[tid];
    float4 r;
    r.x = (v.x - mean) * rs * g4.x + b4.x;
    r.y = (v.y - mean) * rs * g4.y + b4.y;
    r.z = (v.z - mean) * rs * g4.z + b4.z;
    r.w = (v.w - mean) * rs * g4.w + b4.w;
    ((float4*)(out + (size_t)row * DMODEL))[tid] = r;
    if (MODE == 0) {
        uint2 w;
        w.x = pack_h2(r.x, r.y);
        w.y = pack_h2(r.z, r.w);
        ((uint2*)(g_hh + (size_t)row * (DMODEL/2)))[tid] = w;
    }
}

/* ================================================================= */
extern "C" void kernel_launch(void* const* d_in, const int* in_sizes, int n_in,
                              void* d_out, int out_size)
{
    const float* x    = (const float*)d_in[0];
    const float* Wq   = (const float*)d_in[1];
    const float* bq   = (const float*)d_in[2];
    const float* Wk   = (const float*)d_in[3];
    const float* bk   = (const float*)d_in[4];
    const float* Wv   = (const float*)d_in[5];
    const float* bv   = (const float*)d_in[6];
    const float* ln1g = (const float*)d_in[7];
    const float* ln1b = (const float*)d_in[8];
    const float* Wf1  = (const float*)d_in[9];
    const float* bf1  = (const float*)d_in[10];
    const float* Wf2  = (const float*)d_in[11];
    const float* bf2  = (const float*)d_in[12];
    const float* ln2g = (const float*)d_in[13];
    const float* ln2b = (const float*)d_in[14];
    (void)in_sizes; (void)n_in; (void)out_size;

    float* out       = (float*)d_out;                    /* [16384,512]   */
    float* out_score = out + (size_t)MROWS * DMODEL;     /* [16,8192,257] */

    uint32_t *pxh, *pwq, *pwk, *pwv, *pw1, *pw2;
    cudaGetSymbolAddress((void**)&pxh, g_xh);
    cudaGetSymbolAddress((void**)&pwq, g_wqh);
    cudaGetSymbolAddress((void**)&pwk, g_wkh);
    cudaGetSymbolAddress((void**)&pwv, g_wvh);
    cudaGetSymbolAddress((void**)&pw1, g_w1h);
    cudaGetSymbolAddress((void**)&pw2, g_w2h);

    cudaFuncSetAttribute(mma_gemm<0>, cudaFuncAttributeMaxDynamicSharedMemorySize, GEMM_SMEM);
    cudaFuncSetAttribute(mma_gemm<1>, cudaFuncAttributeMaxDynamicSharedMemorySize, GEMM_SMEM);
    cudaFuncSetAttribute(mma_gemm<2>, cudaFuncAttributeMaxDynamicSharedMemorySize, GEMM_SMEM);

    /* 0. pack operands to fp16 */
    {
        int nw;
        nw = MROWS*DMODEL/2;
        pack_a<<<(nw + 255)/256, 256>>>(x, pxh, nw);
        nw = (DMODEL/2)*DMODEL;
        pack_b<<<(nw + 255)/256, 256>>>(Wq, pwq, DMODEL, nw);
        pack_b<<<(nw + 255)/256, 256>>>(Wk, pwk, DMODEL, nw);
        pack_b<<<(nw + 255)/256, 256>>>(Wv, pwv, DMODEL, nw);
        nw = (DMODEL/2)*DHID;
        pack_b<<<(nw + 255)/256, 256>>>(Wf1, pw1, DHID, nw);
        nw = (DHID/2)*DMODEL;
        pack_b<<<(nw + 255)/256, 256>>>(Wf2, pw2, DMODEL, nw);
    }

    /* 1. QKV projections (fp16 m16n8k16) */
    mma_gemm<0><<<dim3(DMODEL/128, MROWS/128, 3), 256, GEMM_SMEM>>>(bq, bk, bv);
    /* 2. attention (tf32 tensor-core) */
    attn_kernel<<<dim3(SEQ/64, BH), 256>>>(out_score);
    /* 3. normalize band */
    band_norm<<<BH*SEQ, 128>>>(out_score);
    /* 4. h = LN(attn + x)  (fp32 + packed half) */
    ln_res<0><<<MROWS, 128>>>(x, ln1g, ln1b, nullptr);
    /* 5. ff1 = relu(h @ Wf1 + bf1) -> packed half */
    mma_gemm<1><<<dim3(DHID/128, MROWS/128), 256, GEMM_SMEM>>>(bf1, nullptr, nullptr);
    /* 6. ff2 = ff1 @ Wf2 + bf2 */
    mma_gemm<2><<<dim3(DMODEL/128, MROWS/128), 256, GEMM_SMEM>>>(bf2, nullptr, nullptr);
    /* 7. out = LN(ff2 + h) */
    ln_res<1><<<MROWS, 128>>>(x, ln2g, ln2b, out);
}